// round 2
// baseline (speedup 1.0000x reference)
#include <cuda_runtime.h>
#include <cstdint>
#include <cstddef>

// ============================================================================
// MaskedLinear: y = x @ (W*mask)^T + b
//   M = 8192 (4*2048), K = 4096, N = 4096, all fp32.
//
// K1: g_wm = cvt.rna.tf32(W*mask)   (fold mask, round-to-nearest tf32)
// K2: g_xr = cvt.rna.tf32(x)
// K3: tiled GEMM, BM=128 x BN=256, BK=32 floats, 4-stage cp.async pipeline.
//     - sm_103a pass (__CUDA_ARCH_FEAT_SM103_ALL): tcgen05 kind::tf32 SS MMA,
//       D in TMEM, LDTM epilogue + bias.
//     - base sm_103 pass: mma.sync.m16n8k8 tf32 (family-portable HMMA),
//       register accumulators, same smem layout.
// ============================================================================

#define SWZ(o) ((o) ^ (((o) >> 3) & 0x70))

static constexpr int BM = 128;
static constexpr int BN = 256;
static constexpr int BK = 32;               // floats per K-chunk (= 128 bytes)
static constexpr int THREADS = 256;
static constexpr int STAGES = 4;

static constexpr int A_BYTES = BM * 128;                  // 16384
static constexpr int B_BYTES = BN * 128;                  // 32768
static constexpr int STAGE_BYTES = A_BYTES + B_BYTES;     // 49152
static constexpr int SMEM_STAGE0 = 1024;
static constexpr int SMEM_TOTAL = SMEM_STAGE0 + STAGES * STAGE_BYTES; // 197632

static constexpr int TMEM_COLS = 256;

// idesc kind::tf32: dfmt=F32(1)<<4, atype=TF32(2)<<7, btype=TF32(2)<<10,
// N>>3 <<17, M>>4 <<24, K-major both.
static constexpr uint32_t IDESC =
    (1u << 4) | (2u << 7) | (2u << 10) | ((BN / 8) << 17) | ((BM / 16) << 24);

// SW128 K-major smem descriptor base: layout=SW128(2), version=1, SBO=64, LBO=1
static constexpr uint64_t DESC_BASE =
    (2ULL << 61) | (1ULL << 46) | (64ULL << 32) | (1ULL << 16);

__device__ float g_wm[4096ull * 4096ull];    // 64 MiB scratch
__device__ float g_xr[8192ull * 4096ull];    // 128 MiB scratch

// ---------------------------------------------------------------------------
// helpers (portable)
// ---------------------------------------------------------------------------
__device__ __forceinline__ uint32_t smem_u32(const void* p) {
    uint32_t a;
    asm("{ .reg .u64 t; cvta.to.shared.u64 t, %1; cvt.u32.u64 %0, t; }"
        : "=r"(a) : "l"(p));
    return a;
}

__device__ __forceinline__ float to_tf32_rn(float x) {
    uint32_t u;
    asm("cvt.rna.tf32.f32 %0, %1;" : "=r"(u) : "f"(x));
    return __uint_as_float(u);
}

__device__ __forceinline__ void cp16(uint32_t s, const float* g) {
    asm volatile("cp.async.cg.shared.global [%0], [%1], 16;"
                 :: "r"(s), "l"(__cvta_generic_to_global((const void*)g)));
}

__device__ __forceinline__ void cpasync_wait_n(int n) {
    if (n <= 0)      asm volatile("cp.async.wait_group 0;" ::: "memory");
    else if (n == 1) asm volatile("cp.async.wait_group 1;" ::: "memory");
    else             asm volatile("cp.async.wait_group 2;" ::: "memory");
}

__device__ __forceinline__ uint32_t lds_u32(uint32_t addr) {
    uint32_t v;
    asm volatile("ld.shared.b32 %0, [%1];" : "=r"(v) : "r"(addr));
    return v;
}

// Load one K-chunk (A: 128x32 f32, B: 256x32 f32) into stage `buf`.
__device__ __forceinline__ void load_stage(uint32_t sb, int buf, int chunk,
                                           int m0, int n0, int K, int tid) {
    const int k0 = chunk * BK;
    const uint32_t sa  = sb + SMEM_STAGE0 + buf * STAGE_BYTES;
    const uint32_t sbm = sa + A_BYTES;
    const float* gA = g_xr + (size_t)m0 * K + k0;
#pragma unroll
    for (int i = 0; i < 4; i++) {
        int u = tid + i * THREADS;            // 0..1023
        int row = u >> 3, seg = u & 7;
        uint32_t off = (uint32_t)(row * 128 + seg * 16);
        cp16(sa + SWZ(off), gA + (size_t)row * K + seg * 4);
    }
    const float* gB = g_wm + (size_t)n0 * K + k0;
#pragma unroll
    for (int i = 0; i < 8; i++) {
        int u = tid + i * THREADS;            // 0..2047
        int row = u >> 3, seg = u & 7;
        uint32_t off = (uint32_t)(row * 128 + seg * 16);
        cp16(sbm + SWZ(off), gB + (size_t)row * K + seg * 4);
    }
    asm volatile("cp.async.commit_group;" ::: "memory");
}

// ---------------------------------------------------------------------------
// sm_103a-only pieces
// ---------------------------------------------------------------------------
#if defined(__CUDA_ARCH_FEAT_SM103_ALL) || defined(__CUDA_ARCH_FEAT_SM100_ALL) || !defined(__CUDA_ARCH__)

__device__ __forceinline__ uint32_t elect_one() {
    uint32_t p;
    asm volatile(
        "{\n\t.reg .pred p;\n\telect.sync _|p, 0xFFFFFFFF;\n\t"
        "selp.b32 %0, 1, 0, p;\n\t}" : "=r"(p));
    return p;
}

__device__ __forceinline__ void mma_tf32(uint32_t d_tmem, uint64_t a_desc,
                                         uint64_t b_desc, uint32_t en) {
#if defined(__CUDA_ARCH__)
    asm volatile(
        "{\n\t.reg .pred p;\n\tsetp.ne.u32 p, %5, 0;\n\t"
        "tcgen05.mma.cta_group::1.kind::tf32 [%0], %1, %2, %3, "
        "{%4, %4, %4, %4}, p;\n\t}"
        :: "r"(d_tmem), "l"(a_desc), "l"(b_desc), "r"(IDESC), "r"(0u), "r"(en)
        : "memory");
#endif
}

#define MBARRIER_INIT(addr, cnt) \
    asm volatile("mbarrier.init.shared.b64 [%0], %1;" :: "r"(addr), "r"(cnt) : "memory")

#define MBARRIER_WAIT_PARITY(addr, ph) do {                                   \
    uint32_t _m = (uint32_t)(addr); uint32_t _p = (uint32_t)(ph);             \
    uint32_t _d;                                                              \
    asm volatile("{\n\t.reg .pred p;\n\t"                                     \
        "mbarrier.try_wait.parity.acquire.cta.shared::cta.b64 p, [%1], %2;\n\t" \
        "selp.b32 %0, 1, 0, p;\n\t}" : "=r"(_d) : "r"(_m), "r"(_p) : "memory"); \
    if (!_d) {                                                                \
        asm volatile("{\n\t.reg .pred P1;\n\t"                                \
            "WL_%=:\n\t"                                                      \
            "mbarrier.try_wait.parity.acquire.cta.shared::cta.b64 P1, [%0], %1, 0x989680;\n\t" \
            "@P1 bra.uni WD_%=;\n\t"                                          \
            "bra.uni WL_%=;\n\t"                                              \
            "WD_%=:\n\t}" :: "r"(_m), "r"(_p) : "memory");                    \
    }                                                                         \
} while (0)

#define TCGEN05_COMMIT(addr) \
    asm volatile("tcgen05.commit.cta_group::1.mbarrier::arrive::one.shared::cluster.b64 [%0];" \
        :: "r"(addr) : "memory")

#define LDTM_X32(r, addr)                                                     \
    asm volatile("tcgen05.ld.sync.aligned.32x32b.x32.b32 "                    \
        "{%0, %1, %2, %3, %4, %5, %6, %7, "                                   \
        " %8, %9, %10, %11, %12, %13, %14, %15, "                             \
        " %16, %17, %18, %19, %20, %21, %22, %23, "                           \
        " %24, %25, %26, %27, %28, %29, %30, %31}, [%32];"                    \
        : "=r"((r)[0]),  "=r"((r)[1]),  "=r"((r)[2]),  "=r"((r)[3]),          \
          "=r"((r)[4]),  "=r"((r)[5]),  "=r"((r)[6]),  "=r"((r)[7]),          \
          "=r"((r)[8]),  "=r"((r)[9]),  "=r"((r)[10]), "=r"((r)[11]),         \
          "=r"((r)[12]), "=r"((r)[13]), "=r"((r)[14]), "=r"((r)[15]),         \
          "=r"((r)[16]), "=r"((r)[17]), "=r"((r)[18]), "=r"((r)[19]),         \
          "=r"((r)[20]), "=r"((r)[21]), "=r"((r)[22]), "=r"((r)[23]),         \
          "=r"((r)[24]), "=r"((r)[25]), "=r"((r)[26]), "=r"((r)[27]),         \
          "=r"((r)[28]), "=r"((r)[29]), "=r"((r)[30]), "=r"((r)[31])          \
        : "r"(addr))

#endif // sm_103a-only pieces

// ---------------------------------------------------------------------------
// prep kernels
// ---------------------------------------------------------------------------
__global__ void prep_w_kernel(const float4* __restrict__ w,
                              const float4* __restrict__ m, int n4) {
    int i = blockIdx.x * blockDim.x + threadIdx.x;
    if (i >= n4) return;
    float4 a = w[i], b = m[i], r;
    r.x = to_tf32_rn(a.x * b.x);
    r.y = to_tf32_rn(a.y * b.y);
    r.z = to_tf32_rn(a.z * b.z);
    r.w = to_tf32_rn(a.w * b.w);
    reinterpret_cast<float4*>(g_wm)[i] = r;
}

__global__ void prep_x_kernel(const float4* __restrict__ x, int n4) {
    int i = blockIdx.x * blockDim.x + threadIdx.x;
    if (i >= n4) return;
    float4 a = x[i], r;
    r.x = to_tf32_rn(a.x);
    r.y = to_tf32_rn(a.y);
    r.z = to_tf32_rn(a.z);
    r.w = to_tf32_rn(a.w);
    reinterpret_cast<float4*>(g_xr)[i] = r;
}

// ---------------------------------------------------------------------------
// main GEMM kernel — dual path
// ---------------------------------------------------------------------------
__global__ void __launch_bounds__(THREADS, 1)
masked_gemm_kernel(const float* __restrict__ bias, float* __restrict__ out,
                   int M, int N, int K) {
    extern __shared__ char smem[];
    const uint32_t sb = smem_u32(smem);
    const int tid = threadIdx.x;
    const int wid = tid >> 5;
    const int lid = tid & 31;
    const int m0 = blockIdx.y * BM;
    const int n0 = blockIdx.x * BN;
    const int KCH = K / BK;   // 128

#if defined(__CUDA_ARCH_FEAT_SM103_ALL) || defined(__CUDA_ARCH_FEAT_SM100_ALL)
    // ============================ tcgen05 path =============================
    if (wid == 0) {
        asm volatile("tcgen05.alloc.cta_group::1.sync.aligned.shared::cta.b32 [%0], %1;"
                     :: "r"(sb), "r"((uint32_t)TMEM_COLS) : "memory");
        asm volatile("tcgen05.relinquish_alloc_permit.cta_group::1.sync.aligned;");
        if (tid == 0) MBARRIER_INIT(sb + 8, 1);
    }
    __syncthreads();
    uint32_t tmem;
    asm volatile("ld.shared.b32 %0, [%1];" : "=r"(tmem) : "r"(sb));

#pragma unroll
    for (int s = 0; s < 3; s++) load_stage(sb, s, s, m0, n0, K, tid);

    for (int k = 0; k < KCH; k++) {
        int pend = KCH - 1 - k; if (pend > 2) pend = 2;
        cpasync_wait_n(pend);
        __syncthreads();

        if (wid == 0) {
            asm volatile("fence.proxy.async.shared::cta;" ::: "memory");
            if (elect_one()) {
                const uint32_t sa  = sb + SMEM_STAGE0 + (k & 3) * STAGE_BYTES;
                const uint64_t ad  = DESC_BASE | ((sa >> 4) & 0x3FFF);
                const uint64_t bd  = DESC_BASE | (((sa + A_BYTES) >> 4) & 0x3FFF);
#pragma unroll
                for (int ks = 0; ks < 4; ks++)
                    mma_tf32(tmem, ad + ks * 2, bd + ks * 2,
                             (uint32_t)(k > 0 || ks > 0));
                TCGEN05_COMMIT(sb + 8);
            }
        }

        if (k > 0) MBARRIER_WAIT_PARITY(sb + 8, (k - 1) & 1);
        if (k + 3 < KCH) load_stage(sb, (k + 3) & 3, k + 3, m0, n0, K, tid);
    }

    MBARRIER_WAIT_PARITY(sb + 8, (KCH - 1) & 1);
    asm volatile("tcgen05.fence::after_thread_sync;" ::: "memory");

    const int sub = wid & 3;
    const int half = wid >> 2;
    const int m = m0 + sub * 32 + lid;
#pragma unroll
    for (int cc = 0; cc < 128; cc += 32) {
        const int col = half * 128 + cc;
        uint32_t r[32];
        LDTM_X32(r, tmem + (uint32_t)col);
        asm volatile("tcgen05.wait::ld.sync.aligned;" ::: "memory");
        const float4* bp = reinterpret_cast<const float4*>(bias + n0 + col);
        float4* op = reinterpret_cast<float4*>(out + (size_t)m * N + n0 + col);
#pragma unroll
        for (int j = 0; j < 8; j++) {
            float4 bv = bp[j];
            float4 v;
            v.x = __uint_as_float(r[4 * j + 0]) + bv.x;
            v.y = __uint_as_float(r[4 * j + 1]) + bv.y;
            v.z = __uint_as_float(r[4 * j + 2]) + bv.z;
            v.w = __uint_as_float(r[4 * j + 3]) + bv.w;
            op[j] = v;
        }
    }

    asm volatile("tcgen05.fence::before_thread_sync;" ::: "memory");
    __syncthreads();
    if (wid == 0) {
        asm volatile("tcgen05.dealloc.cta_group::1.sync.aligned.b32 %0, %1;"
                     :: "r"(tmem), "r"((uint32_t)TMEM_COLS));
    }

#else
    // ======================= mma.sync tf32 fallback ========================
    // 8 warps: warp_m = wid&1 (2 x 64 rows), warp_n = wid>>1 (4 x 64 cols).
    // Per warp: 4 m-tiles (16) x 8 n-tiles (8), k step 8.
    const int wm = (wid & 1) * 64;
    const int wn = (wid >> 1) * 64;
    const int g  = lid >> 2;       // 0..7
    const int t  = lid & 3;        // 0..3

    float acc[4][8][4];
#pragma unroll
    for (int i = 0; i < 4; i++)
#pragma unroll
        for (int j = 0; j < 8; j++)
#pragma unroll
            for (int c = 0; c < 4; c++) acc[i][j][c] = 0.0f;

#pragma unroll
    for (int s = 0; s < 3; s++) load_stage(sb, s, s, m0, n0, K, tid);

    for (int k = 0; k < KCH; k++) {
        int pend = KCH - 1 - k; if (pend > 2) pend = 2;
        cpasync_wait_n(pend);
        __syncthreads();      // also guarantees prev iter's compute done in all warps

        if (k + 3 < KCH) load_stage(sb, (k + 3) & 3, k + 3, m0, n0, K, tid);

        const uint32_t sa = sb + SMEM_STAGE0 + (k & 3) * STAGE_BYTES;
        const uint32_t sB = sa + A_BYTES;

#pragma unroll
        for (int k8 = 0; k8 < 4; k8++) {
            const int kc = k8 * 8;
            uint32_t a[4][4];
#pragma unroll
            for (int mt = 0; mt < 4; mt++) {
                const int r0 = wm + mt * 16 + g;
                const int c0 = kc + t;
                a[mt][0] = lds_u32(sa + SWZ((uint32_t)(r0 * 128 + c0 * 4)));
                a[mt][1] = lds_u32(sa + SWZ((uint32_t)((r0 + 8) * 128 + c0 * 4)));
                a[mt][2] = lds_u32(sa + SWZ((uint32_t)(r0 * 128 + (c0 + 4) * 4)));
                a[mt][3] = lds_u32(sa + SWZ((uint32_t)((r0 + 8) * 128 + (c0 + 4) * 4)));
            }
            uint32_t b[8][2];
#pragma unroll
            for (int nt = 0; nt < 8; nt++) {
                const int n = wn + nt * 8 + g;
                const int ck = kc + t;
                b[nt][0] = lds_u32(sB + SWZ((uint32_t)(n * 128 + ck * 4)));
                b[nt][1] = lds_u32(sB + SWZ((uint32_t)(n * 128 + (ck + 4) * 4)));
            }
#pragma unroll
            for (int mt = 0; mt < 4; mt++)
#pragma unroll
                for (int nt = 0; nt < 8; nt++) {
                    asm volatile(
                        "mma.sync.aligned.m16n8k8.row.col.f32.tf32.tf32.f32 "
                        "{%0,%1,%2,%3}, {%4,%5,%6,%7}, {%8,%9}, {%0,%1,%2,%3};"
                        : "+f"(acc[mt][nt][0]), "+f"(acc[mt][nt][1]),
                          "+f"(acc[mt][nt][2]), "+f"(acc[mt][nt][3])
                        : "r"(a[mt][0]), "r"(a[mt][1]), "r"(a[mt][2]), "r"(a[mt][3]),
                          "r"(b[nt][0]), "r"(b[nt][1]));
                }
        }
    }

    // epilogue: D[16x8] frag: c0/c1 at row g, cols 2t,2t+1; c2/c3 at row g+8.
#pragma unroll
    for (int mt = 0; mt < 4; mt++) {
        const int row0 = m0 + wm + mt * 16 + g;
#pragma unroll
        for (int nt = 0; nt < 8; nt++) {
            const int col0 = n0 + wn + nt * 8 + t * 2;
            const float2 bv = *reinterpret_cast<const float2*>(bias + col0);
            float2 v0, v1;
            v0.x = acc[mt][nt][0] + bv.x;
            v0.y = acc[mt][nt][1] + bv.y;
            v1.x = acc[mt][nt][2] + bv.x;
            v1.y = acc[mt][nt][3] + bv.y;
            *reinterpret_cast<float2*>(out + (size_t)row0 * N + col0) = v0;
            *reinterpret_cast<float2*>(out + (size_t)(row0 + 8) * N + col0) = v1;
        }
    }
#endif
}

// ---------------------------------------------------------------------------
// launch
// ---------------------------------------------------------------------------
extern "C" void kernel_launch(void* const* d_in, const int* in_sizes, int n_in,
                              void* d_out, int out_size) {
    const float* x    = (const float*)d_in[0];
    const float* w    = (const float*)d_in[1];
    const float* bias = (const float*)d_in[2];
    const float* mask = (const float*)d_in[3];
    float* out = (float*)d_out;

    const int N = in_sizes[2];                  // 4096 (D_OUT)
    const int K = in_sizes[1] / N;              // 4096 (D_IN)
    const int M = in_sizes[0] / K;              // 8192 (B*S)

    {
        int n4 = (N * K) / 4;
        prep_w_kernel<<<(n4 + 255) / 256, 256>>>((const float4*)w,
                                                 (const float4*)mask, n4);
    }
    {
        int n4 = (M * K) / 4;
        prep_x_kernel<<<(n4 + 255) / 256, 256>>>((const float4*)x, n4);
    }

    cudaFuncSetAttribute(masked_gemm_kernel,
                         cudaFuncAttributeMaxDynamicSharedMemorySize, SMEM_TOTAL);
    dim3 grid(N / BN, M / BM);   // (16, 64)
    masked_gemm_kernel<<<grid, THREADS, SMEM_TOTAL>>>(bias, out, M, N, K);
}

// round 3
// speedup vs baseline: 1.1232x; 1.1232x over previous
#include <cuda_runtime.h>
#include <cstdint>
#include <cstddef>

// ============================================================================
// MaskedLinear: y = x @ (W*mask)^T + b ; M=8192, K=4096, N=4096 fp32.
//
// prep_w: g_wm = cvt.rna.tf32(W*mask)  (RN pre-round; MMA then truncates losslessly)
// gemm  : cg2 (2-CTA) tcgen05 kind::tf32 SS GEMM, pair tile 256x256, BK=32,
//         6-stage cp.async pipeline, x read directly (HW RZ to tf32),
//         D in TMEM (256 fp32 cols/CTA), bias epilogue.
// Fallback (non-103a PTX pass only; never selected on GB300): mma.sync tf32.
// ============================================================================

#define SWZ(o) ((o) ^ (((o) >> 3) & 0x70))

static constexpr int BK = 32;                // floats per K-chunk (128 B)
static constexpr int THREADS = 256;

// --- cg2 main path ---
static constexpr int STAGES = 6;
static constexpr int A_BYTES = 128 * 128;    // 16 KB (128 rows x 128 B)
static constexpr int B_BYTES = 128 * 128;    // 16 KB
static constexpr int STAGE_BYTES = A_BYTES + B_BYTES;            // 32768
static constexpr int SMEM_STAGE0 = 1024;
static constexpr int SMEM_TOTAL = SMEM_STAGE0 + STAGES * STAGE_BYTES; // 197632
static constexpr int TMEM_COLS = 256;

// idesc kind::tf32 cg2: dfmt=F32(1)<<4, atype=TF32(2)<<7, btype=TF32(2)<<10,
// N=256 -> 32<<17, M=256 -> 16<<24.
static constexpr uint32_t IDESC =
    (1u << 4) | (2u << 7) | (2u << 10) | (32u << 17) | (16u << 24);

// SW128 K-major smem descriptor: layout=SW128(2), version=1, SBO=64, LBO=1
static constexpr uint64_t DESC_BASE =
    (2ULL << 61) | (1ULL << 46) | (64ULL << 32) | (1ULL << 16);

// mbar offsets: ready[s] @ 16+8s (leader), done[s] @ 80+8s (both CTAs)
#define READY_OFF(s) (16u + (uint32_t)(s) * 8u)
#define DONE_OFF(s)  (80u + (uint32_t)(s) * 8u)

// --- fallback layout (compiles on base sm_103; unused on device) ---
static constexpr int FB_STAGES = 4;
static constexpr int FB_A_BYTES = 128 * 128;          // 16 KB
static constexpr int FB_B_BYTES = 256 * 128;          // 32 KB
static constexpr int FB_STAGE_BYTES = FB_A_BYTES + FB_B_BYTES;   // 49152
// SMEM_STAGE0 + 4*49152 == 197632 == SMEM_TOTAL

__device__ float g_wm[4096ull * 4096ull];    // 64 MiB scratch

// ---------------------------------------------------------------------------
// portable helpers
// ---------------------------------------------------------------------------
__device__ __forceinline__ uint32_t smem_u32(const void* p) {
    uint32_t a;
    asm("{ .reg .u64 t; cvta.to.shared.u64 t, %1; cvt.u32.u64 %0, t; }"
        : "=r"(a) : "l"(p));
    return a;
}

__device__ __forceinline__ float to_tf32_rn(float x) {
    uint32_t u;
    asm("cvt.rna.tf32.f32 %0, %1;" : "=r"(u) : "f"(x));
    return __uint_as_float(u);
}

__device__ __forceinline__ void cp16(uint32_t s, const float* g) {
    asm volatile("cp.async.cg.shared.global [%0], [%1], 16;"
                 :: "r"(s), "l"(__cvta_generic_to_global((const void*)g)));
}

__device__ __forceinline__ void cpasync_wait_n(int n) {
    if (n <= 0)      asm volatile("cp.async.wait_group 0;" ::: "memory");
    else if (n == 1) asm volatile("cp.async.wait_group 1;" ::: "memory");
    else if (n == 2) asm volatile("cp.async.wait_group 2;" ::: "memory");
    else if (n == 3) asm volatile("cp.async.wait_group 3;" ::: "memory");
    else             asm volatile("cp.async.wait_group 4;" ::: "memory");
}

__device__ __forceinline__ uint32_t lds_u32(uint32_t addr) {
    uint32_t v;
    asm volatile("ld.shared.b32 %0, [%1];" : "=r"(v) : "r"(addr));
    return v;
}

#define CLUSTER_SYNC() do {                                          \
    asm volatile("barrier.cluster.arrive.aligned;" ::: "memory");    \
    asm volatile("barrier.cluster.wait.aligned;" ::: "memory");      \
} while (0)

// cg2 path stage load: A 128x32 f32 + B 128x32 f32 (4+4 cp16 per thread)
__device__ __forceinline__ void load_stage(uint32_t sb, int buf,
                                           const float* gA, const float* gB,
                                           int K, int tid) {
    const uint32_t sa  = sb + SMEM_STAGE0 + buf * STAGE_BYTES;
    const uint32_t sbm = sa + A_BYTES;
#pragma unroll
    for (int i = 0; i < 4; i++) {
        int u = tid + i * THREADS;
        int row = u >> 3, seg = u & 7;
        uint32_t off = (uint32_t)(row * 128 + seg * 16);
        cp16(sa + SWZ(off), gA + (size_t)row * K + seg * 4);
    }
#pragma unroll
    for (int i = 0; i < 4; i++) {
        int u = tid + i * THREADS;
        int row = u >> 3, seg = u & 7;
        uint32_t off = (uint32_t)(row * 128 + seg * 16);
        cp16(sbm + SWZ(off), gB + (size_t)row * K + seg * 4);
    }
    asm volatile("cp.async.commit_group;" ::: "memory");
}

// fallback stage load: A 128x32 + B 256x32
__device__ __forceinline__ void load_stage_fb(uint32_t sb, int buf,
                                              const float* gA, const float* gB,
                                              int K, int tid) {
    const uint32_t sa  = sb + SMEM_STAGE0 + buf * FB_STAGE_BYTES;
    const uint32_t sbm = sa + FB_A_BYTES;
#pragma unroll
    for (int i = 0; i < 4; i++) {
        int u = tid + i * THREADS;
        int row = u >> 3, seg = u & 7;
        uint32_t off = (uint32_t)(row * 128 + seg * 16);
        cp16(sa + SWZ(off), gA + (size_t)row * K + seg * 4);
    }
#pragma unroll
    for (int i = 0; i < 8; i++) {
        int u = tid + i * THREADS;
        int row = u >> 3, seg = u & 7;
        uint32_t off = (uint32_t)(row * 128 + seg * 16);
        cp16(sbm + SWZ(off), gB + (size_t)row * K + seg * 4);
    }
    asm volatile("cp.async.commit_group;" ::: "memory");
}

// ---------------------------------------------------------------------------
// sm_103a-only pieces
// ---------------------------------------------------------------------------
#if defined(__CUDA_ARCH_FEAT_SM103_ALL) || defined(__CUDA_ARCH_FEAT_SM100_ALL) || !defined(__CUDA_ARCH__)

__device__ __forceinline__ uint32_t elect_one() {
    uint32_t p;
    asm volatile(
        "{\n\t.reg .pred p;\n\telect.sync _|p, 0xFFFFFFFF;\n\t"
        "selp.b32 %0, 1, 0, p;\n\t}" : "=r"(p));
    return p;
}

__device__ __forceinline__ void mma_tf32_cg2(uint32_t d_tmem, uint64_t a_desc,
                                             uint64_t b_desc, uint32_t en) {
#if defined(__CUDA_ARCH__)
    asm volatile(
        "{\n\t.reg .pred p;\n\tsetp.ne.u32 p, %6, 0;\n\t"
        "tcgen05.mma.cta_group::2.kind::tf32 [%0], %1, %2, %3, "
        "{%4, %4, %4, %4, %4, %4, %4, %4}, p;\n\t}"
        :: "r"(d_tmem), "l"(a_desc), "l"(b_desc), "r"(IDESC),
           "r"(0u), "r"(0u), "r"(en)
        : "memory");
#endif
}

#define MBARRIER_INIT(addr, cnt) \
    asm volatile("mbarrier.init.shared.b64 [%0], %1;" :: "r"(addr), "r"(cnt) : "memory")

// local (cta-scope acquire) parity wait — used for done bars
#define MBARRIER_WAIT_PARITY(addr, ph) do {                                   \
    uint32_t _m = (uint32_t)(addr); uint32_t _p = (uint32_t)(ph);             \
    uint32_t _d;                                                              \
    asm volatile("{\n\t.reg .pred p;\n\t"                                     \
        "mbarrier.try_wait.parity.acquire.cta.shared::cta.b64 p, [%1], %2;\n\t" \
        "selp.b32 %0, 1, 0, p;\n\t}" : "=r"(_d) : "r"(_m), "r"(_p) : "memory"); \
    if (!_d) {                                                                \
        asm volatile("{\n\t.reg .pred P1;\n\t"                                \
            "WL_%=:\n\t"                                                      \
            "mbarrier.try_wait.parity.acquire.cta.shared::cta.b64 P1, [%0], %1, 0x989680;\n\t" \
            "@P1 bra.uni WD_%=;\n\t"                                          \
            "bra.uni WL_%=;\n\t"                                              \
            "WD_%=:\n\t}" :: "r"(_m), "r"(_p) : "memory");                    \
    }                                                                         \
} while (0)

// cluster-scope acquire parity wait — leader waits follower's ready arrival
#define MBARRIER_WAIT_PARITY_CLUSTER(addr, ph) do {                           \
    uint32_t _m = (uint32_t)(addr); uint32_t _p = (uint32_t)(ph);             \
    uint32_t _d;                                                              \
    asm volatile("{\n\t.reg .pred p;\n\t"                                     \
        "mbarrier.try_wait.parity.acquire.cluster.shared::cta.b64 p, [%1], %2;\n\t" \
        "selp.b32 %0, 1, 0, p;\n\t}" : "=r"(_d) : "r"(_m), "r"(_p) : "memory"); \
    if (!_d) {                                                                \
        asm volatile("{\n\t.reg .pred P1;\n\t"                                \
            "WLc_%=:\n\t"                                                     \
            "mbarrier.try_wait.parity.acquire.cluster.shared::cta.b64 P1, [%0], %1, 0x989680;\n\t" \
            "@P1 bra.uni WDc_%=;\n\t"                                         \
            "bra.uni WLc_%=;\n\t"                                             \
            "WDc_%=:\n\t}" :: "r"(_m), "r"(_p) : "memory");                   \
    }                                                                         \
} while (0)

// follower arrives on the leader's (rank 0) mbar at the same smem offset
#define MBARRIER_ARRIVE_RANK0(addr)                                           \
    asm volatile("{\n\t.reg .b32 r;\n\t"                                      \
        "mapa.shared::cluster.u32 r, %0, 0;\n\t"                              \
        "mbarrier.arrive.shared::cluster.b64 _, [r];\n\t}"                    \
        :: "r"((uint32_t)(addr)) : "memory")

#define TCGEN05_COMMIT_MC_CG2(addr, mask)                                     \
    asm volatile("tcgen05.commit.cta_group::2.mbarrier::arrive::one.shared::cluster.multicast::cluster.b64 [%0], %1;" \
        :: "r"((uint32_t)(addr)), "h"((uint16_t)(mask)) : "memory")

#define LDTM_X32(r, addr)                                                     \
    asm volatile("tcgen05.ld.sync.aligned.32x32b.x32.b32 "                    \
        "{%0, %1, %2, %3, %4, %5, %6, %7, "                                   \
        " %8, %9, %10, %11, %12, %13, %14, %15, "                             \
        " %16, %17, %18, %19, %20, %21, %22, %23, "                           \
        " %24, %25, %26, %27, %28, %29, %30, %31}, [%32];"                    \
        : "=r"((r)[0]),  "=r"((r)[1]),  "=r"((r)[2]),  "=r"((r)[3]),          \
          "=r"((r)[4]),  "=r"((r)[5]),  "=r"((r)[6]),  "=r"((r)[7]),          \
          "=r"((r)[8]),  "=r"((r)[9]),  "=r"((r)[10]), "=r"((r)[11]),         \
          "=r"((r)[12]), "=r"((r)[13]), "=r"((r)[14]), "=r"((r)[15]),         \
          "=r"((r)[16]), "=r"((r)[17]), "=r"((r)[18]), "=r"((r)[19]),         \
          "=r"((r)[20]), "=r"((r)[21]), "=r"((r)[22]), "=r"((r)[23]),         \
          "=r"((r)[24]), "=r"((r)[25]), "=r"((r)[26]), "=r"((r)[27]),         \
          "=r"((r)[28]), "=r"((r)[29]), "=r"((r)[30]), "=r"((r)[31])          \
        : "r"(addr))

#endif // sm_103a-only pieces

// ---------------------------------------------------------------------------
// prep kernel: fold mask, RN-round W to tf32
// ---------------------------------------------------------------------------
__global__ void prep_w_kernel(const float4* __restrict__ w,
                              const float4* __restrict__ m, int n4) {
    int i = blockIdx.x * blockDim.x + threadIdx.x;
    if (i >= n4) return;
    float4 a = w[i], b = m[i], r;
    r.x = to_tf32_rn(a.x * b.x);
    r.y = to_tf32_rn(a.y * b.y);
    r.z = to_tf32_rn(a.z * b.z);
    r.w = to_tf32_rn(a.w * b.w);
    reinterpret_cast<float4*>(g_wm)[i] = r;
}

// ---------------------------------------------------------------------------
// main GEMM kernel — cg2 tcgen05 / fallback mma.sync
// ---------------------------------------------------------------------------
__global__ void __launch_bounds__(THREADS, 1) __cluster_dims__(2, 1, 1)
masked_gemm_kernel(const float* __restrict__ x, const float* __restrict__ bias,
                   float* __restrict__ out, int M, int N, int K) {
    extern __shared__ char smem[];
    const uint32_t sb = smem_u32(smem);
    const int tid = threadIdx.x;
    const int wid = tid >> 5;
    const int lid = tid & 31;
    const int rank = blockIdx.x;                      // cluster rank (0/1)
    const int m0 = blockIdx.z * 256 + rank * 128;     // this CTA's 128 M-rows
    const int n0 = blockIdx.y * 256;                  // pair's N tile
    const int KCH = K / BK;                           // 128

#if defined(__CUDA_ARCH_FEAT_SM103_ALL) || defined(__CUDA_ARCH_FEAT_SM100_ALL)
    // ============================ cg2 tcgen05 path ==========================
    const float* gA0 = x + (size_t)m0 * K;                        // raw x (HW RZ)
    const float* gB0 = g_wm + (size_t)(n0 + rank * 128) * K;      // this CTA's B half

    if (wid == 0) {
        asm volatile("tcgen05.alloc.cta_group::2.sync.aligned.shared::cta.b32 [%0], %1;"
                     :: "r"(sb), "r"((uint32_t)TMEM_COLS) : "memory");
        asm volatile("tcgen05.relinquish_alloc_permit.cta_group::2.sync.aligned;");
    }
    if (tid == 0) {
#pragma unroll
        for (int s = 0; s < STAGES; s++) {
            MBARRIER_INIT(sb + READY_OFF(s), 1);
            MBARRIER_INIT(sb + DONE_OFF(s), 1);
        }
    }
    __syncthreads();
    uint32_t tmem;
    asm volatile("ld.shared.b32 %0, [%1];" : "=r"(tmem) : "r"(sb));
    CLUSTER_SYNC();   // mbars visible cluster-wide before any arrivals/commits

    // prologue: STAGES-1 = 5 chunks in flight
#pragma unroll
    for (int s = 0; s < STAGES - 1; s++)
        load_stage(sb, s, gA0 + s * BK, gB0 + s * BK, K, tid);

    int lstage = STAGES - 1;              // buffer for chunk k+5
    int mstage = 0; uint32_t mph = 0;     // ready/desc stage for chunk k
    int dstage = 0; uint32_t dph = 0;     // done stage for chunk k-1

    for (int k = 0; k < KCH; k++) {
        int pend = KCH - 1 - k; if (pend > STAGES - 2) pend = STAGES - 2;
        cpasync_wait_n(pend);             // chunk k local data complete
        __syncthreads();

        if (wid == 0) {
            asm volatile("fence.proxy.async.shared::cta;" ::: "memory");
            if (elect_one()) {
                if (rank == 0) {
                    // wait follower's chunk-k data, then MMA over both CTAs' smem
                    MBARRIER_WAIT_PARITY_CLUSTER(sb + READY_OFF(mstage), mph);
                    const uint32_t sa = sb + SMEM_STAGE0 + mstage * STAGE_BYTES;
                    const uint64_t ad = DESC_BASE | ((sa >> 4) & 0x3FFF);
                    const uint64_t bd = DESC_BASE | (((sa + A_BYTES) >> 4) & 0x3FFF);
#pragma unroll
                    for (int ks = 0; ks < 4; ks++)
                        mma_tf32_cg2(tmem, ad + ks * 2, bd + ks * 2,
                                     (uint32_t)(k > 0 || ks > 0));
                    TCGEN05_COMMIT_MC_CG2(sb + DONE_OFF(mstage), 0x3);
                } else {
                    MBARRIER_ARRIVE_RANK0(sb + READY_OFF(mstage));
                }
            }
        }
        if (++mstage == STAGES) { mstage = 0; mph ^= 1; }

        if (k > 0) {                       // MMA(k-1) done -> its buffer reusable
            MBARRIER_WAIT_PARITY(sb + DONE_OFF(dstage), dph);
            if (++dstage == STAGES) { dstage = 0; dph ^= 1; }
        }
        if (k + STAGES - 1 < KCH) {
            const int c = k + STAGES - 1;
            load_stage(sb, lstage, gA0 + (size_t)c * BK, gB0 + (size_t)c * BK, K, tid);
            if (++lstage == STAGES) lstage = 0;
        }
    }
    MBARRIER_WAIT_PARITY(sb + DONE_OFF(dstage), dph);   // last MMA done
    asm volatile("tcgen05.fence::after_thread_sync;" ::: "memory");

    // epilogue: 8 warps; warp&3 = TMEM subpartition, warp>>2 = column half
    {
        const int sub = wid & 3;
        const int half = wid >> 2;
        const int m = m0 + sub * 32 + lid;
#pragma unroll
        for (int cc = 0; cc < 128; cc += 32) {
            const int col = half * 128 + cc;
            uint32_t r[32];
            LDTM_X32(r, tmem + (uint32_t)col);
            asm volatile("tcgen05.wait::ld.sync.aligned;" ::: "memory");
            const float4* bp = reinterpret_cast<const float4*>(bias + n0 + col);
            float4* op = reinterpret_cast<float4*>(out + (size_t)m * N + n0 + col);
#pragma unroll
            for (int j = 0; j < 8; j++) {
                float4 bv = bp[j];
                float4 v;
                v.x = __uint_as_float(r[4 * j + 0]) + bv.x;
                v.y = __uint_as_float(r[4 * j + 1]) + bv.y;
                v.z = __uint_as_float(r[4 * j + 2]) + bv.z;
                v.w = __uint_as_float(r[4 * j + 3]) + bv.w;
                op[j] = v;
            }
        }
    }

    asm volatile("tcgen05.fence::before_thread_sync;" ::: "memory");
    __syncthreads();
    if (wid == 0) {
        asm volatile("tcgen05.dealloc.cta_group::2.sync.aligned.b32 %0, %1;"
                     :: "r"(tmem), "r"((uint32_t)TMEM_COLS));
    }
    CLUSTER_SYNC();

#else
    // ======================= mma.sync tf32 fallback ========================
    // Each CTA independently computes its 128 x 256 block (full B tile loaded).
    const float* gA0 = x + (size_t)m0 * K;
    const float* gB0 = g_wm + (size_t)n0 * K;

    const int wm = (wid & 1) * 64;
    const int wn = (wid >> 1) * 64;
    const int g  = lid >> 2;
    const int t  = lid & 3;

    float acc[4][8][4];
#pragma unroll
    for (int i = 0; i < 4; i++)
#pragma unroll
        for (int j = 0; j < 8; j++)
#pragma unroll
            for (int c = 0; c < 4; c++) acc[i][j][c] = 0.0f;

#pragma unroll
    for (int s = 0; s < 3; s++)
        load_stage_fb(sb, s, gA0 + s * BK, gB0 + s * BK, K, tid);

    for (int k = 0; k < KCH; k++) {
        int pend = KCH - 1 - k; if (pend > 2) pend = 2;
        cpasync_wait_n(pend);
        __syncthreads();

        if (k + 3 < KCH) {
            const int c = k + 3;
            load_stage_fb(sb, (k + 3) & 3, gA0 + (size_t)c * BK, gB0 + (size_t)c * BK, K, tid);
        }

        const uint32_t sa = sb + SMEM_STAGE0 + (k & 3) * FB_STAGE_BYTES;
        const uint32_t sB = sa + FB_A_BYTES;

#pragma unroll
        for (int k8 = 0; k8 < 4; k8++) {
            const int kc = k8 * 8;
            uint32_t a[4][4];
#pragma unroll
            for (int mt = 0; mt < 4; mt++) {
                const int r0 = wm + mt * 16 + g;
                const int c0 = kc + t;
                a[mt][0] = lds_u32(sa + SWZ((uint32_t)(r0 * 128 + c0 * 4)));
                a[mt][1] = lds_u32(sa + SWZ((uint32_t)((r0 + 8) * 128 + c0 * 4)));
                a[mt][2] = lds_u32(sa + SWZ((uint32_t)(r0 * 128 + (c0 + 4) * 4)));
                a[mt][3] = lds_u32(sa + SWZ((uint32_t)((r0 + 8) * 128 + (c0 + 4) * 4)));
            }
            uint32_t b[8][2];
#pragma unroll
            for (int nt = 0; nt < 8; nt++) {
                const int n = wn + nt * 8 + g;
                const int ck = kc + t;
                b[nt][0] = lds_u32(sB + SWZ((uint32_t)(n * 128 + ck * 4)));
                b[nt][1] = lds_u32(sB + SWZ((uint32_t)(n * 128 + (ck + 4) * 4)));
            }
#pragma unroll
            for (int mt = 0; mt < 4; mt++)
#pragma unroll
                for (int nt = 0; nt < 8; nt++) {
                    asm volatile(
                        "mma.sync.aligned.m16n8k8.row.col.f32.tf32.tf32.f32 "
                        "{%0,%1,%2,%3}, {%4,%5,%6,%7}, {%8,%9}, {%0,%1,%2,%3};"
                        : "+f"(acc[mt][nt][0]), "+f"(acc[mt][nt][1]),
                          "+f"(acc[mt][nt][2]), "+f"(acc[mt][nt][3])
                        : "r"(a[mt][0]), "r"(a[mt][1]), "r"(a[mt][2]), "r"(a[mt][3]),
                          "r"(b[nt][0]), "r"(b[nt][1]));
                }
        }
    }

#pragma unroll
    for (int mt = 0; mt < 4; mt++) {
        const int row0 = m0 + wm + mt * 16 + g;
#pragma unroll
        for (int nt = 0; nt < 8; nt++) {
            const int col0 = n0 + wn + nt * 8 + t * 2;
            const float2 bv = *reinterpret_cast<const float2*>(bias + col0);
            float2 v0, v1;
            v0.x = acc[mt][nt][0] + bv.x;
            v0.y = acc[mt][nt][1] + bv.y;
            v1.x = acc[mt][nt][2] + bv.x;
            v1.y = acc[mt][nt][3] + bv.y;
            *reinterpret_cast<float2*>(out + (size_t)row0 * N + col0) = v0;
            *reinterpret_cast<float2*>(out + (size_t)(row0 + 8) * N + col0) = v1;
        }
    }
#endif
}

// ---------------------------------------------------------------------------
// launch
// ---------------------------------------------------------------------------
extern "C" void kernel_launch(void* const* d_in, const int* in_sizes, int n_in,
                              void* d_out, int out_size) {
    const float* x    = (const float*)d_in[0];
    const float* w    = (const float*)d_in[1];
    const float* bias = (const float*)d_in[2];
    const float* mask = (const float*)d_in[3];
    float* out = (float*)d_out;

    const int N = in_sizes[2];                  // 4096 (D_OUT)
    const int K = in_sizes[1] / N;              // 4096 (D_IN)
    const int M = in_sizes[0] / K;              // 8192 (B*S)

    {
        int n4 = (N * K) / 4;
        prep_w_kernel<<<(n4 + 255) / 256, 256>>>((const float4*)w,
                                                 (const float4*)mask, n4);
    }

    cudaFuncSetAttribute(masked_gemm_kernel,
                         cudaFuncAttributeMaxDynamicSharedMemorySize, SMEM_TOTAL);
    dim3 grid(2, N / 256, M / 256);   // (2, 16, 32) — cluster pairs along x
    masked_gemm_kernel<<<grid, THREADS, SMEM_TOTAL>>>(x, bias, out, M, N, K);
}

// round 4
// speedup vs baseline: 1.2588x; 1.1207x over previous
#include <cuda_runtime.h>
#include <cstdint>
#include <cstddef>

// ============================================================================
// MaskedLinear: y = x @ (W*mask)^T + b ; M=8192, K=4096, N=4096 fp32.
//
// prep_w: g_wm = cvt.rna.tf32(W*mask)  (RN pre-round; MMA truncation lossless)
// gemm  : cg2 tcgen05 kind::tf32 SS GEMM, pair tile 256x256, BK=32,
//         WARP-SPECIALIZED: warps 0-7 = cp.async producers, warp 8 = MMA issue.
//         6-stage full/done mbarrier ring, no per-chunk __syncthreads.
//         x read raw (HW RZ->tf32), W pre-rounded RN.
// Fallback (non-103a PTX pass; never selected on GB300): mma.sync tf32.
// ============================================================================

#define SWZ(o) ((o) ^ (((o) >> 3) & 0x70))

static constexpr int BK = 32;                 // floats per K-chunk (128 B)
static constexpr int THREADS = 288;           // 8 loader warps + 1 MMA warp
static constexpr int NLOAD = 256;             // loader thread count

static constexpr int STAGES = 6;
static constexpr int A_BYTES = 128 * 128;     // 16 KB
static constexpr int B_BYTES = 128 * 128;     // 16 KB
static constexpr int STAGE_BYTES = A_BYTES + B_BYTES;                 // 32 KB
static constexpr int SMEM_STAGE0 = 1024;
static constexpr int SMEM_TOTAL = SMEM_STAGE0 + STAGES * STAGE_BYTES; // 197632
static constexpr int TMEM_COLS = 256;

// idesc kind::tf32 cg2: dfmt=F32(1)<<4, atype=TF32(2)<<7, btype=TF32(2)<<10,
// N=256 -> 32<<17, M=256 -> 16<<24.
static constexpr uint32_t IDESC =
    (1u << 4) | (2u << 7) | (2u << 10) | (32u << 17) | (16u << 24);

// SW128 K-major smem descriptor: layout=SW128(2), version=1, SBO=64, LBO=1
static constexpr uint64_t DESC_BASE =
    (2ULL << 61) | (1ULL << 46) | (64ULL << 32) | (1ULL << 16);

#define FULL_OFF(s) (16u + (uint32_t)(s) * 8u)   // leader: 16 arrivals/stage
#define DONE_OFF(s) (80u + (uint32_t)(s) * 8u)   // both CTAs: commit target

// --- fallback layout (base sm_103 pass only) ---
static constexpr int FB_A_BYTES = 128 * 128;
static constexpr int FB_B_BYTES = 256 * 128;
static constexpr int FB_STAGE_BYTES = FB_A_BYTES + FB_B_BYTES;   // 49152

__device__ float g_wm[4096ull * 4096ull];    // 64 MiB scratch

// ---------------------------------------------------------------------------
// portable helpers
// ---------------------------------------------------------------------------
__device__ __forceinline__ uint32_t smem_u32(const void* p) {
    uint32_t a;
    asm("{ .reg .u64 t; cvta.to.shared.u64 t, %1; cvt.u32.u64 %0, t; }"
        : "=r"(a) : "l"(p));
    return a;
}

__device__ __forceinline__ float to_tf32_rn(float x) {
    uint32_t u;
    asm("cvt.rna.tf32.f32 %0, %1;" : "=r"(u) : "f"(x));
    return __uint_as_float(u);
}

__device__ __forceinline__ void cp16(uint32_t s, const float* g) {
    asm volatile("cp.async.cg.shared.global [%0], [%1], 16;"
                 :: "r"(s), "l"(__cvta_generic_to_global((const void*)g)));
}

__device__ __forceinline__ uint32_t lds_u32(uint32_t addr) {
    uint32_t v;
    asm volatile("ld.shared.b32 %0, [%1];" : "=r"(v) : "r"(addr));
    return v;
}

#define CLUSTER_SYNC() do {                                          \
    asm volatile("barrier.cluster.arrive.aligned;" ::: "memory");    \
    asm volatile("barrier.cluster.wait.aligned;" ::: "memory");      \
} while (0)

// cg2 stage load: A 128x32 f32 + B 128x32 f32, 256 loader threads (4+4 cp16)
__device__ __forceinline__ void load_stage(uint32_t sb, int buf,
                                           const float* gA, const float* gB,
                                           int K, int ltid) {
    const uint32_t sa  = sb + SMEM_STAGE0 + buf * STAGE_BYTES;
    const uint32_t sbm = sa + A_BYTES;
#pragma unroll
    for (int i = 0; i < 4; i++) {
        int u = ltid + i * NLOAD;
        int row = u >> 3, seg = u & 7;
        uint32_t off = (uint32_t)(row * 128 + seg * 16);
        cp16(sa + SWZ(off), gA + (size_t)row * K + seg * 4);
    }
#pragma unroll
    for (int i = 0; i < 4; i++) {
        int u = ltid + i * NLOAD;
        int row = u >> 3, seg = u & 7;
        uint32_t off = (uint32_t)(row * 128 + seg * 16);
        cp16(sbm + SWZ(off), gB + (size_t)row * K + seg * 4);
    }
    asm volatile("cp.async.commit_group;" ::: "memory");
}

// fallback stage load: A 128x32 + B 256x32
__device__ __forceinline__ void load_stage_fb(uint32_t sb, int buf,
                                              const float* gA, const float* gB,
                                              int K, int ltid) {
    const uint32_t sa  = sb + SMEM_STAGE0 + buf * FB_STAGE_BYTES;
    const uint32_t sbm = sa + FB_A_BYTES;
#pragma unroll
    for (int i = 0; i < 4; i++) {
        int u = ltid + i * NLOAD;
        int row = u >> 3, seg = u & 7;
        uint32_t off = (uint32_t)(row * 128 + seg * 16);
        cp16(sa + SWZ(off), gA + (size_t)row * K + seg * 4);
    }
#pragma unroll
    for (int i = 0; i < 8; i++) {
        int u = ltid + i * NLOAD;
        int row = u >> 3, seg = u & 7;
        uint32_t off = (uint32_t)(row * 128 + seg * 16);
        cp16(sbm + SWZ(off), gB + (size_t)row * K + seg * 4);
    }
    asm volatile("cp.async.commit_group;" ::: "memory");
}

// ---------------------------------------------------------------------------
// sm_103a-only pieces
// ---------------------------------------------------------------------------
#if defined(__CUDA_ARCH_FEAT_SM103_ALL) || defined(__CUDA_ARCH_FEAT_SM100_ALL) || !defined(__CUDA_ARCH__)

__device__ __forceinline__ uint32_t elect_one() {
    uint32_t p;
    asm volatile(
        "{\n\t.reg .pred p;\n\telect.sync _|p, 0xFFFFFFFF;\n\t"
        "selp.b32 %0, 1, 0, p;\n\t}" : "=r"(p));
    return p;
}

__device__ __forceinline__ void mma_tf32_cg2(uint32_t d_tmem, uint64_t a_desc,
                                             uint64_t b_desc, uint32_t en) {
#if defined(__CUDA_ARCH__)
    asm volatile(
        "{\n\t.reg .pred p;\n\tsetp.ne.u32 p, %6, 0;\n\t"
        "tcgen05.mma.cta_group::2.kind::tf32 [%0], %1, %2, %3, "
        "{%4, %4, %4, %4, %4, %4, %4, %4}, p;\n\t}"
        :: "r"(d_tmem), "l"(a_desc), "l"(b_desc), "r"(IDESC),
           "r"(0u), "r"(0u), "r"(en)
        : "memory");
#endif
}

#define MBARRIER_INIT(addr, cnt) \
    asm volatile("mbarrier.init.shared.b64 [%0], %1;" :: "r"(addr), "r"(cnt) : "memory")

// cta-scope acquire parity wait (done bars)
#define MBARRIER_WAIT_PARITY(addr, ph) do {                                   \
    uint32_t _m = (uint32_t)(addr); uint32_t _p = (uint32_t)(ph);             \
    uint32_t _d;                                                              \
    asm volatile("{\n\t.reg .pred p;\n\t"                                     \
        "mbarrier.try_wait.parity.acquire.cta.shared::cta.b64 p, [%1], %2;\n\t" \
        "selp.b32 %0, 1, 0, p;\n\t}" : "=r"(_d) : "r"(_m), "r"(_p) : "memory"); \
    if (!_d) {                                                                \
        asm volatile("{\n\t.reg .pred P1;\n\t"                                \
            "WL_%=:\n\t"                                                      \
            "mbarrier.try_wait.parity.acquire.cta.shared::cta.b64 P1, [%0], %1, 0x989680;\n\t" \
            "@P1 bra.uni WD_%=;\n\t"                                          \
            "bra.uni WL_%=;\n\t"                                              \
            "WD_%=:\n\t}" :: "r"(_m), "r"(_p) : "memory");                    \
    }                                                                         \
} while (0)

// cluster-scope acquire parity wait (full bars: remote producers arrive)
#define MBARRIER_WAIT_PARITY_CLUSTER(addr, ph) do {                           \
    uint32_t _m = (uint32_t)(addr); uint32_t _p = (uint32_t)(ph);             \
    uint32_t _d;                                                              \
    asm volatile("{\n\t.reg .pred p;\n\t"                                     \
        "mbarrier.try_wait.parity.acquire.cluster.shared::cta.b64 p, [%1], %2;\n\t" \
        "selp.b32 %0, 1, 0, p;\n\t}" : "=r"(_d) : "r"(_m), "r"(_p) : "memory"); \
    if (!_d) {                                                                \
        asm volatile("{\n\t.reg .pred P1;\n\t"                                \
            "WLc_%=:\n\t"                                                     \
            "mbarrier.try_wait.parity.acquire.cluster.shared::cta.b64 P1, [%0], %1, 0x989680;\n\t" \
            "@P1 bra.uni WDc_%=;\n\t"                                         \
            "bra.uni WLc_%=;\n\t"                                             \
            "WDc_%=:\n\t}" :: "r"(_m), "r"(_p) : "memory");                   \
    }                                                                         \
} while (0)

#define MBARRIER_ARRIVE_LOCAL(addr)                                           \
    asm volatile("mbarrier.arrive.shared.b64 _, [%0];"                        \
        :: "r"((uint32_t)(addr)) : "memory")

#define MBARRIER_ARRIVE_RANK0(addr)                                           \
    asm volatile("{\n\t.reg .b32 r;\n\t"                                      \
        "mapa.shared::cluster.u32 r, %0, 0;\n\t"                              \
        "mbarrier.arrive.shared::cluster.b64 _, [r];\n\t}"                    \
        :: "r"((uint32_t)(addr)) : "memory")

#define TCGEN05_COMMIT_MC_CG2(addr, mask)                                     \
    asm volatile("tcgen05.commit.cta_group::2.mbarrier::arrive::one.shared::cluster.multicast::cluster.b64 [%0], %1;" \
        :: "r"((uint32_t)(addr)), "h"((uint16_t)(mask)) : "memory")

#define LDTM_X32(r, addr)                                                     \
    asm volatile("tcgen05.ld.sync.aligned.32x32b.x32.b32 "                    \
        "{%0, %1, %2, %3, %4, %5, %6, %7, "                                   \
        " %8, %9, %10, %11, %12, %13, %14, %15, "                             \
        " %16, %17, %18, %19, %20, %21, %22, %23, "                           \
        " %24, %25, %26, %27, %28, %29, %30, %31}, [%32];"                    \
        : "=r"((r)[0]),  "=r"((r)[1]),  "=r"((r)[2]),  "=r"((r)[3]),          \
          "=r"((r)[4]),  "=r"((r)[5]),  "=r"((r)[6]),  "=r"((r)[7]),          \
          "=r"((r)[8]),  "=r"((r)[9]),  "=r"((r)[10]), "=r"((r)[11]),         \
          "=r"((r)[12]), "=r"((r)[13]), "=r"((r)[14]), "=r"((r)[15]),         \
          "=r"((r)[16]), "=r"((r)[17]), "=r"((r)[18]), "=r"((r)[19]),         \
          "=r"((r)[20]), "=r"((r)[21]), "=r"((r)[22]), "=r"((r)[23]),         \
          "=r"((r)[24]), "=r"((r)[25]), "=r"((r)[26]), "=r"((r)[27]),         \
          "=r"((r)[28]), "=r"((r)[29]), "=r"((r)[30]), "=r"((r)[31])          \
        : "r"(addr))

#endif // sm_103a-only pieces

// ---------------------------------------------------------------------------
// prep kernel: fold mask, RN-round W to tf32
// ---------------------------------------------------------------------------
__global__ void prep_w_kernel(const float4* __restrict__ w,
                              const float4* __restrict__ m, int n4) {
    int i = blockIdx.x * blockDim.x + threadIdx.x;
    if (i >= n4) return;
    float4 a = w[i], b = m[i], r;
    r.x = to_tf32_rn(a.x * b.x);
    r.y = to_tf32_rn(a.y * b.y);
    r.z = to_tf32_rn(a.z * b.z);
    r.w = to_tf32_rn(a.w * b.w);
    reinterpret_cast<float4*>(g_wm)[i] = r;
}

// ---------------------------------------------------------------------------
// main GEMM kernel
// ---------------------------------------------------------------------------
__global__ void __launch_bounds__(THREADS, 1) __cluster_dims__(2, 1, 1)
masked_gemm_kernel(const float* __restrict__ x, const float* __restrict__ bias,
                   float* __restrict__ out, int M, int N, int K) {
    extern __shared__ char smem[];
    const uint32_t sb = smem_u32(smem);
    const int tid = threadIdx.x;
    const int wid = tid >> 5;
    const int lid = tid & 31;
    const int rank = blockIdx.x;                      // cluster rank (0/1)
    const int m0 = blockIdx.z * 256 + rank * 128;
    const int n0 = blockIdx.y * 256;
    const int KCH = K / BK;                           // 128

#if defined(__CUDA_ARCH_FEAT_SM103_ALL) || defined(__CUDA_ARCH_FEAT_SM100_ALL)
    // ===================== warp-specialized cg2 path =======================
    const float* gA0 = x + (size_t)m0 * K;                    // raw x (HW RZ)
    const float* gB0 = g_wm + (size_t)(n0 + rank * 128) * K;  // this CTA's B half

    if (wid == 8) {
        asm volatile("tcgen05.alloc.cta_group::2.sync.aligned.shared::cta.b32 [%0], %1;"
                     :: "r"(sb), "r"((uint32_t)TMEM_COLS) : "memory");
        asm volatile("tcgen05.relinquish_alloc_permit.cta_group::2.sync.aligned;");
    }
    if (tid == 0) {
#pragma unroll
        for (int s = 0; s < STAGES; s++) {
            MBARRIER_INIT(sb + FULL_OFF(s), 16);   // 8 local + 8 remote warps
            MBARRIER_INIT(sb + DONE_OFF(s), 1);    // tcgen05 commit
        }
    }
    __syncthreads();
    uint32_t tmem;
    asm volatile("ld.shared.b32 %0, [%1];" : "=r"(tmem) : "r"(sb));
    CLUSTER_SYNC();   // mbars live cluster-wide before any remote arrival

    if (wid < 8) {
        // ------------------------- producer warps --------------------------
        int dst = 0; uint32_t dph = 0;     // done-ring cursor (buffer reuse)
        int ast = 4;                       // arrival stage cursor: (c-2)%6 starts
                                           // at c=2 -> 0; track directly below.
        (void)ast;
        int arr_s = 0;                     // stage of next full-arrival (chunk c-2)
        for (int c = 0; c < KCH; c++) {
            if (c >= STAGES) {             // buffer (c%6) freed by MMA c-6
                MBARRIER_WAIT_PARITY(sb + DONE_OFF(dst), dph);
                if (++dst == STAGES) { dst = 0; dph ^= 1; }
            }
            load_stage(sb, c % STAGES, gA0 + (size_t)c * BK,
                       gB0 + (size_t)c * BK, K, tid);
            if (c >= 2) {                  // signal chunk c-2 complete
                asm volatile("cp.async.wait_group 2;" ::: "memory");
                asm volatile("fence.proxy.async.shared::cta;" ::: "memory");
                if (elect_one()) {
                    if (rank == 0) MBARRIER_ARRIVE_LOCAL(sb + FULL_OFF(arr_s));
                    else           MBARRIER_ARRIVE_RANK0(sb + FULL_OFF(arr_s));
                }
                if (++arr_s == STAGES) arr_s = 0;
            }
        }
        // tail: signal last two chunks
        asm volatile("cp.async.wait_group 1;" ::: "memory");
        asm volatile("fence.proxy.async.shared::cta;" ::: "memory");
        if (elect_one()) {
            if (rank == 0) MBARRIER_ARRIVE_LOCAL(sb + FULL_OFF(arr_s));
            else           MBARRIER_ARRIVE_RANK0(sb + FULL_OFF(arr_s));
        }
        if (++arr_s == STAGES) arr_s = 0;
        asm volatile("cp.async.wait_group 0;" ::: "memory");
        asm volatile("fence.proxy.async.shared::cta;" ::: "memory");
        if (elect_one()) {
            if (rank == 0) MBARRIER_ARRIVE_LOCAL(sb + FULL_OFF(arr_s));
            else           MBARRIER_ARRIVE_RANK0(sb + FULL_OFF(arr_s));
        }
        // wait final MMA, then epilogue
        MBARRIER_WAIT_PARITY(sb + DONE_OFF((KCH - 1) % STAGES),
                             ((KCH - 1) / STAGES) & 1);
        asm volatile("tcgen05.fence::after_thread_sync;" ::: "memory");

        const int sub = wid & 3;
        const int half = wid >> 2;
        const int m = m0 + sub * 32 + lid;
#pragma unroll
        for (int cc = 0; cc < 128; cc += 32) {
            const int col = half * 128 + cc;
            uint32_t r[32];
            LDTM_X32(r, tmem + (uint32_t)col);
            asm volatile("tcgen05.wait::ld.sync.aligned;" ::: "memory");
            const float4* bp = reinterpret_cast<const float4*>(bias + n0 + col);
            float4* op = reinterpret_cast<float4*>(out + (size_t)m * N + n0 + col);
#pragma unroll
            for (int j = 0; j < 8; j++) {
                float4 bv = bp[j];
                float4 v;
                v.x = __uint_as_float(r[4 * j + 0]) + bv.x;
                v.y = __uint_as_float(r[4 * j + 1]) + bv.y;
                v.z = __uint_as_float(r[4 * j + 2]) + bv.z;
                v.w = __uint_as_float(r[4 * j + 3]) + bv.w;
                op[j] = v;
            }
        }
        asm volatile("tcgen05.fence::before_thread_sync;" ::: "memory");
    } else {
        // --------------------------- MMA warp ------------------------------
        if (rank == 0) {
            if (elect_one()) {
                int s = 0; uint32_t ph = 0;
                for (int k = 0; k < KCH; k++) {
                    MBARRIER_WAIT_PARITY_CLUSTER(sb + FULL_OFF(s), ph);
                    const uint32_t sa = sb + SMEM_STAGE0 + s * STAGE_BYTES;
                    const uint64_t ad = DESC_BASE | ((sa >> 4) & 0x3FFF);
                    const uint64_t bd = DESC_BASE | (((sa + A_BYTES) >> 4) & 0x3FFF);
#pragma unroll
                    for (int ks = 0; ks < 4; ks++)
                        mma_tf32_cg2(tmem, ad + ks * 2, bd + ks * 2,
                                     (uint32_t)(k > 0 || ks > 0));
                    TCGEN05_COMMIT_MC_CG2(sb + DONE_OFF(s), 0x3);
                    if (++s == STAGES) { s = 0; ph ^= 1; }
                }
            }
        }
    }

    __syncthreads();
    if (wid == 8) {
        asm volatile("tcgen05.dealloc.cta_group::2.sync.aligned.b32 %0, %1;"
                     :: "r"(tmem), "r"((uint32_t)TMEM_COLS));
    }
    CLUSTER_SYNC();

#else
    // ======================= mma.sync tf32 fallback ========================
    const float* gA0 = x + (size_t)m0 * K;
    const float* gB0 = g_wm + (size_t)n0 * K;

    const int wm = (wid & 1) * 64;
    const int wn = (wid >> 1) * 64;
    const int g  = lid >> 2;
    const int t  = lid & 3;

    float acc[4][8][4];
#pragma unroll
    for (int i = 0; i < 4; i++)
#pragma unroll
        for (int j = 0; j < 8; j++)
#pragma unroll
            for (int c = 0; c < 4; c++) acc[i][j][c] = 0.0f;

    if (tid < NLOAD) {
#pragma unroll
        for (int s = 0; s < 3; s++)
            load_stage_fb(sb, s, gA0 + s * BK, gB0 + s * BK, K, tid);
    }

    for (int k = 0; k < KCH; k++) {
        if (tid < NLOAD) {
            int pend = KCH - 1 - k; if (pend > 2) pend = 2;
            if (pend <= 0)      asm volatile("cp.async.wait_group 0;" ::: "memory");
            else if (pend == 1) asm volatile("cp.async.wait_group 1;" ::: "memory");
            else                asm volatile("cp.async.wait_group 2;" ::: "memory");
        }
        __syncthreads();

        if (tid < NLOAD && k + 3 < KCH) {
            const int c = k + 3;
            load_stage_fb(sb, (k + 3) & 3, gA0 + (size_t)c * BK,
                          gB0 + (size_t)c * BK, K, tid);
        }

        if (wid < 8) {
            const uint32_t sa = sb + SMEM_STAGE0 + (k & 3) * FB_STAGE_BYTES;
            const uint32_t sB = sa + FB_A_BYTES;
#pragma unroll
            for (int k8 = 0; k8 < 4; k8++) {
                const int kc = k8 * 8;
                uint32_t a[4][4];
#pragma unroll
                for (int mt = 0; mt < 4; mt++) {
                    const int r0 = wm + mt * 16 + g;
                    const int c0 = kc + t;
                    a[mt][0] = lds_u32(sa + SWZ((uint32_t)(r0 * 128 + c0 * 4)));
                    a[mt][1] = lds_u32(sa + SWZ((uint32_t)((r0 + 8) * 128 + c0 * 4)));
                    a[mt][2] = lds_u32(sa + SWZ((uint32_t)(r0 * 128 + (c0 + 4) * 4)));
                    a[mt][3] = lds_u32(sa + SWZ((uint32_t)((r0 + 8) * 128 + (c0 + 4) * 4)));
                }
                uint32_t b[8][2];
#pragma unroll
                for (int nt = 0; nt < 8; nt++) {
                    const int n = wn + nt * 8 + g;
                    const int ck = kc + t;
                    b[nt][0] = lds_u32(sB + SWZ((uint32_t)(n * 128 + ck * 4)));
                    b[nt][1] = lds_u32(sB + SWZ((uint32_t)(n * 128 + (ck + 4) * 4)));
                }
#pragma unroll
                for (int mt = 0; mt < 4; mt++)
#pragma unroll
                    for (int nt = 0; nt < 8; nt++) {
                        asm volatile(
                            "mma.sync.aligned.m16n8k8.row.col.f32.tf32.tf32.f32 "
                            "{%0,%1,%2,%3}, {%4,%5,%6,%7}, {%8,%9}, {%0,%1,%2,%3};"
                            : "+f"(acc[mt][nt][0]), "+f"(acc[mt][nt][1]),
                              "+f"(acc[mt][nt][2]), "+f"(acc[mt][nt][3])
                            : "r"(a[mt][0]), "r"(a[mt][1]), "r"(a[mt][2]), "r"(a[mt][3]),
                              "r"(b[nt][0]), "r"(b[nt][1]));
                    }
            }
        }
    }

    if (wid < 8) {
#pragma unroll
        for (int mt = 0; mt < 4; mt++) {
            const int row0 = m0 + wm + mt * 16 + g;
#pragma unroll
            for (int nt = 0; nt < 8; nt++) {
                const int col0 = n0 + wn + nt * 8 + t * 2;
                const float2 bv = *reinterpret_cast<const float2*>(bias + col0);
                float2 v0, v1;
                v0.x = acc[mt][nt][0] + bv.x;
                v0.y = acc[mt][nt][1] + bv.y;
                v1.x = acc[mt][nt][2] + bv.x;
                v1.y = acc[mt][nt][3] + bv.y;
                *reinterpret_cast<float2*>(out + (size_t)row0 * N + col0) = v0;
                *reinterpret_cast<float2*>(out + (size_t)(row0 + 8) * N + col0) = v1;
            }
        }
    }
#endif
}

// ---------------------------------------------------------------------------
// launch
// ---------------------------------------------------------------------------
extern "C" void kernel_launch(void* const* d_in, const int* in_sizes, int n_in,
                              void* d_out, int out_size) {
    const float* x    = (const float*)d_in[0];
    const float* w    = (const float*)d_in[1];
    const float* bias = (const float*)d_in[2];
    const float* mask = (const float*)d_in[3];
    float* out = (float*)d_out;

    const int N = in_sizes[2];                  // 4096 (D_OUT)
    const int K = in_sizes[1] / N;              // 4096 (D_IN)
    const int M = in_sizes[0] / K;              // 8192 (B*S)

    {
        int n4 = (N * K) / 4;
        prep_w_kernel<<<(n4 + 255) / 256, 256>>>((const float4*)w,
                                                 (const float4*)mask, n4);
    }

    cudaFuncSetAttribute(masked_gemm_kernel,
                         cudaFuncAttributeMaxDynamicSharedMemorySize, SMEM_TOTAL);
    dim3 grid(2, N / 256, M / 256);   // (2, 16, 32) — cluster pairs along x
    masked_gemm_kernel<<<grid, THREADS, SMEM_TOTAL>>>(x, bias, out, M, N, K);
}

// round 5
// speedup vs baseline: 1.2740x; 1.0121x over previous
#include <cuda_runtime.h>
#include <cstdint>
#include <cstddef>

// ============================================================================
// MaskedLinear: y = x @ (W*mask)^T + b ; M=8192, K=4096, N=4096 fp32.
//
// prep_w: g_wm = cvt.rna.tf32(W*mask)  (RN pre-round; MMA truncation lossless)
// gemm  : cg2 tcgen05 kind::tf32 SS GEMM, PAIR TILE 256(M) x 512(N):
//         two N=256 MMAs per chunk into D0 (TMEM cols 0-255) / D1 (256-511).
//         Warp-specialized: warps 0-7 producers (cp.async), warp 8 MMA issue.
//         4-stage full/done mbarrier ring. x read raw (HW RZ->tf32).
// Fallback (non-103a PTX pass; never selected on GB300): mma.sync tf32.
// ============================================================================

#define SWZ(o) ((o) ^ (((o) >> 3) & 0x70))

static constexpr int BK = 32;                 // floats per K-chunk (128 B)
static constexpr int THREADS = 288;           // 8 loader warps + 1 MMA warp
static constexpr int NLOAD = 256;

static constexpr int STAGES = 4;
static constexpr int A_BYTES  = 128 * 128;    // 16 KB
static constexpr int B0_BYTES = 128 * 128;    // 16 KB (N half 0, this CTA's rows)
static constexpr int B1_BYTES = 128 * 128;    // 16 KB (N half 1)
static constexpr int STAGE_BYTES = A_BYTES + B0_BYTES + B1_BYTES;     // 48 KB
static constexpr int SMEM_STAGE0 = 1024;
static constexpr int SMEM_TOTAL = SMEM_STAGE0 + STAGES * STAGE_BYTES; // 197632
static constexpr int TMEM_COLS = 512;

// idesc kind::tf32 cg2: dfmt=F32(1)<<4, atype=TF32(2)<<7, btype=TF32(2)<<10,
// N=256 -> 32<<17, M=256 -> 16<<24.
static constexpr uint32_t IDESC =
    (1u << 4) | (2u << 7) | (2u << 10) | (32u << 17) | (16u << 24);

// SW128 K-major smem descriptor: layout=SW128(2), version=1, SBO=64, LBO=1
static constexpr uint64_t DESC_BASE =
    (2ULL << 61) | (1ULL << 46) | (64ULL << 32) | (1ULL << 16);

#define FULL_OFF(s) (16u + (uint32_t)(s) * 8u)   // leader: 16 arrivals/stage
#define DONE_OFF(s) (80u + (uint32_t)(s) * 8u)   // both CTAs: commit target

// --- fallback layout (base sm_103 pass only; never runs on GB300) ---
static constexpr int FB_A_BYTES = 128 * 128;
static constexpr int FB_B_BYTES = 256 * 128;
static constexpr int FB_STAGE_BYTES = FB_A_BYTES + FB_B_BYTES;   // 49152

__device__ float g_wm[4096ull * 4096ull];    // 64 MiB scratch

// ---------------------------------------------------------------------------
// portable helpers
// ---------------------------------------------------------------------------
__device__ __forceinline__ uint32_t smem_u32(const void* p) {
    uint32_t a;
    asm("{ .reg .u64 t; cvta.to.shared.u64 t, %1; cvt.u32.u64 %0, t; }"
        : "=r"(a) : "l"(p));
    return a;
}

__device__ __forceinline__ float to_tf32_rn(float x) {
    uint32_t u;
    asm("cvt.rna.tf32.f32 %0, %1;" : "=r"(u) : "f"(x));
    return __uint_as_float(u);
}

__device__ __forceinline__ void cp16(uint32_t s, const float* g) {
    asm volatile("cp.async.cg.shared.global [%0], [%1], 16;"
                 :: "r"(s), "l"(__cvta_generic_to_global((const void*)g)));
}

__device__ __forceinline__ uint32_t lds_u32(uint32_t addr) {
    uint32_t v;
    asm volatile("ld.shared.b32 %0, [%1];" : "=r"(v) : "r"(addr));
    return v;
}

#define CLUSTER_SYNC() do {                                          \
    asm volatile("barrier.cluster.arrive.aligned;" ::: "memory");    \
    asm volatile("barrier.cluster.wait.aligned;" ::: "memory");      \
} while (0)

// cg2 stage load: A 128x32 + B0 128x32 + B1 128x32 (4+4+4 cp16 per thread)
__device__ __forceinline__ void load_stage(uint32_t sb, int buf,
                                           const float* gA, const float* gB0,
                                           const float* gB1, int K, int ltid) {
    const uint32_t sa  = sb + SMEM_STAGE0 + buf * STAGE_BYTES;
    const uint32_t sb0 = sa + A_BYTES;
    const uint32_t sb1 = sb0 + B0_BYTES;
#pragma unroll
    for (int i = 0; i < 4; i++) {
        int u = ltid + i * NLOAD;
        int row = u >> 3, seg = u & 7;
        uint32_t off = (uint32_t)(row * 128 + seg * 16);
        cp16(sa + SWZ(off), gA + (size_t)row * K + seg * 4);
    }
#pragma unroll
    for (int i = 0; i < 4; i++) {
        int u = ltid + i * NLOAD;
        int row = u >> 3, seg = u & 7;
        uint32_t off = (uint32_t)(row * 128 + seg * 16);
        cp16(sb0 + SWZ(off), gB0 + (size_t)row * K + seg * 4);
    }
#pragma unroll
    for (int i = 0; i < 4; i++) {
        int u = ltid + i * NLOAD;
        int row = u >> 3, seg = u & 7;
        uint32_t off = (uint32_t)(row * 128 + seg * 16);
        cp16(sb1 + SWZ(off), gB1 + (size_t)row * K + seg * 4);
    }
    asm volatile("cp.async.commit_group;" ::: "memory");
}

// fallback stage load: A 128x32 + B 256x32
__device__ __forceinline__ void load_stage_fb(uint32_t sb, int buf,
                                              const float* gA, const float* gB,
                                              int K, int ltid) {
    const uint32_t sa  = sb + SMEM_STAGE0 + buf * FB_STAGE_BYTES;
    const uint32_t sbm = sa + FB_A_BYTES;
#pragma unroll
    for (int i = 0; i < 4; i++) {
        int u = ltid + i * NLOAD;
        int row = u >> 3, seg = u & 7;
        uint32_t off = (uint32_t)(row * 128 + seg * 16);
        cp16(sa + SWZ(off), gA + (size_t)row * K + seg * 4);
    }
#pragma unroll
    for (int i = 0; i < 8; i++) {
        int u = ltid + i * NLOAD;
        int row = u >> 3, seg = u & 7;
        uint32_t off = (uint32_t)(row * 128 + seg * 16);
        cp16(sbm + SWZ(off), gB + (size_t)row * K + seg * 4);
    }
    asm volatile("cp.async.commit_group;" ::: "memory");
}

// ---------------------------------------------------------------------------
// sm_103a-only pieces
// ---------------------------------------------------------------------------
#if defined(__CUDA_ARCH_FEAT_SM103_ALL) || defined(__CUDA_ARCH_FEAT_SM100_ALL) || !defined(__CUDA_ARCH__)

__device__ __forceinline__ uint32_t elect_one() {
    uint32_t p;
    asm volatile(
        "{\n\t.reg .pred p;\n\telect.sync _|p, 0xFFFFFFFF;\n\t"
        "selp.b32 %0, 1, 0, p;\n\t}" : "=r"(p));
    return p;
}

__device__ __forceinline__ void mma_tf32_cg2(uint32_t d_tmem, uint64_t a_desc,
                                             uint64_t b_desc, uint32_t en) {
#if defined(__CUDA_ARCH__)
    asm volatile(
        "{\n\t.reg .pred p;\n\tsetp.ne.u32 p, %6, 0;\n\t"
        "tcgen05.mma.cta_group::2.kind::tf32 [%0], %1, %2, %3, "
        "{%4, %4, %4, %4, %4, %4, %4, %4}, p;\n\t}"
        :: "r"(d_tmem), "l"(a_desc), "l"(b_desc), "r"(IDESC),
           "r"(0u), "r"(0u), "r"(en)
        : "memory");
#endif
}

#define MBARRIER_INIT(addr, cnt) \
    asm volatile("mbarrier.init.shared.b64 [%0], %1;" :: "r"(addr), "r"(cnt) : "memory")

#define MBARRIER_WAIT_PARITY(addr, ph) do {                                   \
    uint32_t _m = (uint32_t)(addr); uint32_t _p = (uint32_t)(ph);             \
    uint32_t _d;                                                              \
    asm volatile("{\n\t.reg .pred p;\n\t"                                     \
        "mbarrier.try_wait.parity.acquire.cta.shared::cta.b64 p, [%1], %2;\n\t" \
        "selp.b32 %0, 1, 0, p;\n\t}" : "=r"(_d) : "r"(_m), "r"(_p) : "memory"); \
    if (!_d) {                                                                \
        asm volatile("{\n\t.reg .pred P1;\n\t"                                \
            "WL_%=:\n\t"                                                      \
            "mbarrier.try_wait.parity.acquire.cta.shared::cta.b64 P1, [%0], %1, 0x989680;\n\t" \
            "@P1 bra.uni WD_%=;\n\t"                                          \
            "bra.uni WL_%=;\n\t"                                              \
            "WD_%=:\n\t}" :: "r"(_m), "r"(_p) : "memory");                    \
    }                                                                         \
} while (0)

#define MBARRIER_WAIT_PARITY_CLUSTER(addr, ph) do {                           \
    uint32_t _m = (uint32_t)(addr); uint32_t _p = (uint32_t)(ph);             \
    uint32_t _d;                                                              \
    asm volatile("{\n\t.reg .pred p;\n\t"                                     \
        "mbarrier.try_wait.parity.acquire.cluster.shared::cta.b64 p, [%1], %2;\n\t" \
        "selp.b32 %0, 1, 0, p;\n\t}" : "=r"(_d) : "r"(_m), "r"(_p) : "memory"); \
    if (!_d) {                                                                \
        asm volatile("{\n\t.reg .pred P1;\n\t"                                \
            "WLc_%=:\n\t"                                                     \
            "mbarrier.try_wait.parity.acquire.cluster.shared::cta.b64 P1, [%0], %1, 0x989680;\n\t" \
            "@P1 bra.uni WDc_%=;\n\t"                                         \
            "bra.uni WLc_%=;\n\t"                                             \
            "WDc_%=:\n\t}" :: "r"(_m), "r"(_p) : "memory");                   \
    }                                                                         \
} while (0)

#define MBARRIER_ARRIVE_LOCAL(addr)                                           \
    asm volatile("mbarrier.arrive.shared.b64 _, [%0];"                        \
        :: "r"((uint32_t)(addr)) : "memory")

#define MBARRIER_ARRIVE_RANK0(addr)                                           \
    asm volatile("{\n\t.reg .b32 r;\n\t"                                      \
        "mapa.shared::cluster.u32 r, %0, 0;\n\t"                              \
        "mbarrier.arrive.shared::cluster.b64 _, [r];\n\t}"                    \
        :: "r"((uint32_t)(addr)) : "memory")

#define TCGEN05_COMMIT_MC_CG2(addr, mask)                                     \
    asm volatile("tcgen05.commit.cta_group::2.mbarrier::arrive::one.shared::cluster.multicast::cluster.b64 [%0], %1;" \
        :: "r"((uint32_t)(addr)), "h"((uint16_t)(mask)) : "memory")

#define LDTM_X32(r, addr)                                                     \
    asm volatile("tcgen05.ld.sync.aligned.32x32b.x32.b32 "                    \
        "{%0, %1, %2, %3, %4, %5, %6, %7, "                                   \
        " %8, %9, %10, %11, %12, %13, %14, %15, "                             \
        " %16, %17, %18, %19, %20, %21, %22, %23, "                           \
        " %24, %25, %26, %27, %28, %29, %30, %31}, [%32];"                    \
        : "=r"((r)[0]),  "=r"((r)[1]),  "=r"((r)[2]),  "=r"((r)[3]),          \
          "=r"((r)[4]),  "=r"((r)[5]),  "=r"((r)[6]),  "=r"((r)[7]),          \
          "=r"((r)[8]),  "=r"((r)[9]),  "=r"((r)[10]), "=r"((r)[11]),         \
          "=r"((r)[12]), "=r"((r)[13]), "=r"((r)[14]), "=r"((r)[15]),         \
          "=r"((r)[16]), "=r"((r)[17]), "=r"((r)[18]), "=r"((r)[19]),         \
          "=r"((r)[20]), "=r"((r)[21]), "=r"((r)[22]), "=r"((r)[23]),         \
          "=r"((r)[24]), "=r"((r)[25]), "=r"((r)[26]), "=r"((r)[27]),         \
          "=r"((r)[28]), "=r"((r)[29]), "=r"((r)[30]), "=r"((r)[31])          \
        : "r"(addr))

#endif // sm_103a-only pieces

// ---------------------------------------------------------------------------
// prep kernel
// ---------------------------------------------------------------------------
__global__ void prep_w_kernel(const float4* __restrict__ w,
                              const float4* __restrict__ m, int n4) {
    int i = blockIdx.x * blockDim.x + threadIdx.x;
    if (i >= n4) return;
    float4 a = w[i], b = m[i], r;
    r.x = to_tf32_rn(a.x * b.x);
    r.y = to_tf32_rn(a.y * b.y);
    r.z = to_tf32_rn(a.z * b.z);
    r.w = to_tf32_rn(a.w * b.w);
    reinterpret_cast<float4*>(g_wm)[i] = r;
}

// ---------------------------------------------------------------------------
// main GEMM kernel
// ---------------------------------------------------------------------------
__global__ void __launch_bounds__(THREADS, 1) __cluster_dims__(2, 1, 1)
masked_gemm_kernel(const float* __restrict__ x, const float* __restrict__ bias,
                   float* __restrict__ out, int M, int N, int K) {
    extern __shared__ char smem[];
    const uint32_t sb = smem_u32(smem);
    const int tid = threadIdx.x;
    const int wid = tid >> 5;
    const int lid = tid & 31;
    const int rank = blockIdx.x;                      // cluster rank (0/1)
    const int m0 = blockIdx.z * 256 + rank * 128;     // this CTA's 128 M-rows
    const int n0 = blockIdx.y * 512;                  // pair's 512-wide N tile
    const int KCH = K / BK;                           // 128

#if defined(__CUDA_ARCH_FEAT_SM103_ALL) || defined(__CUDA_ARCH_FEAT_SM100_ALL)
    // ===================== warp-specialized cg2 path =======================
    const float* gA0  = x + (size_t)m0 * K;
    const float* gB0r = g_wm + (size_t)(n0 + rank * 128) * K;        // MMA0 rows
    const float* gB1r = g_wm + (size_t)(n0 + 256 + rank * 128) * K;  // MMA1 rows

    if (wid == 8) {
        asm volatile("tcgen05.alloc.cta_group::2.sync.aligned.shared::cta.b32 [%0], %1;"
                     :: "r"(sb), "r"((uint32_t)TMEM_COLS) : "memory");
        asm volatile("tcgen05.relinquish_alloc_permit.cta_group::2.sync.aligned;");
    }
    if (tid == 0) {
#pragma unroll
        for (int s = 0; s < STAGES; s++) {
            MBARRIER_INIT(sb + FULL_OFF(s), 16);   // 8 local + 8 remote warps
            MBARRIER_INIT(sb + DONE_OFF(s), 1);
        }
    }
    __syncthreads();
    uint32_t tmem;
    asm volatile("ld.shared.b32 %0, [%1];" : "=r"(tmem) : "r"(sb));
    CLUSTER_SYNC();

    if (wid < 8) {
        // ------------------------- producer warps --------------------------
        int dst = 0; uint32_t dph = 0;     // done cursor (buffer c-4 reuse)
        int arr_s = 0;                     // full-arrival stage (chunk c-2)
        for (int c = 0; c < KCH; c++) {
            if (c >= STAGES) {
                MBARRIER_WAIT_PARITY(sb + DONE_OFF(dst), dph);
                if (++dst == STAGES) { dst = 0; dph ^= 1; }
            }
            load_stage(sb, c % STAGES, gA0 + (size_t)c * BK,
                       gB0r + (size_t)c * BK, gB1r + (size_t)c * BK, K, tid);
            if (c >= 2) {
                asm volatile("cp.async.wait_group 2;" ::: "memory");
                asm volatile("fence.proxy.async.shared::cta;" ::: "memory");
                if (elect_one()) {
                    if (rank == 0) MBARRIER_ARRIVE_LOCAL(sb + FULL_OFF(arr_s));
                    else           MBARRIER_ARRIVE_RANK0(sb + FULL_OFF(arr_s));
                }
                if (++arr_s == STAGES) arr_s = 0;
            }
        }
        asm volatile("cp.async.wait_group 1;" ::: "memory");
        asm volatile("fence.proxy.async.shared::cta;" ::: "memory");
        if (elect_one()) {
            if (rank == 0) MBARRIER_ARRIVE_LOCAL(sb + FULL_OFF(arr_s));
            else           MBARRIER_ARRIVE_RANK0(sb + FULL_OFF(arr_s));
        }
        if (++arr_s == STAGES) arr_s = 0;
        asm volatile("cp.async.wait_group 0;" ::: "memory");
        asm volatile("fence.proxy.async.shared::cta;" ::: "memory");
        if (elect_one()) {
            if (rank == 0) MBARRIER_ARRIVE_LOCAL(sb + FULL_OFF(arr_s));
            else           MBARRIER_ARRIVE_RANK0(sb + FULL_OFF(arr_s));
        }
        // wait final MMA, then epilogue over 512 cols
        MBARRIER_WAIT_PARITY(sb + DONE_OFF((KCH - 1) % STAGES),
                             ((KCH - 1) / STAGES) & 1);
        asm volatile("tcgen05.fence::after_thread_sync;" ::: "memory");

        const int sub = wid & 3;
        const int half = wid >> 2;            // 0: cols 0-255, 1: cols 256-511
        const int m = m0 + sub * 32 + lid;
#pragma unroll
        for (int cc = 0; cc < 256; cc += 32) {
            const int col = half * 256 + cc;
            uint32_t r[32];
            LDTM_X32(r, tmem + (uint32_t)col);
            asm volatile("tcgen05.wait::ld.sync.aligned;" ::: "memory");
            const float4* bp = reinterpret_cast<const float4*>(bias + n0 + col);
            float4* op = reinterpret_cast<float4*>(out + (size_t)m * N + n0 + col);
#pragma unroll
            for (int j = 0; j < 8; j++) {
                float4 bv = bp[j];
                float4 v;
                v.x = __uint_as_float(r[4 * j + 0]) + bv.x;
                v.y = __uint_as_float(r[4 * j + 1]) + bv.y;
                v.z = __uint_as_float(r[4 * j + 2]) + bv.z;
                v.w = __uint_as_float(r[4 * j + 3]) + bv.w;
                op[j] = v;
            }
        }
        asm volatile("tcgen05.fence::before_thread_sync;" ::: "memory");
    } else {
        // --------------------------- MMA warp ------------------------------
        if (rank == 0) {
            if (elect_one()) {
                int s = 0; uint32_t ph = 0;
                for (int k = 0; k < KCH; k++) {
                    MBARRIER_WAIT_PARITY_CLUSTER(sb + FULL_OFF(s), ph);
                    const uint32_t sa = sb + SMEM_STAGE0 + s * STAGE_BYTES;
                    const uint64_t ad  = DESC_BASE | ((sa >> 4) & 0x3FFF);
                    const uint64_t b0d = DESC_BASE | (((sa + A_BYTES) >> 4) & 0x3FFF);
                    const uint64_t b1d = DESC_BASE | (((sa + A_BYTES + B0_BYTES) >> 4) & 0x3FFF);
                    const uint32_t en = (uint32_t)(k > 0);
#pragma unroll
                    for (int ks = 0; ks < 4; ks++) {
                        uint32_t e = en | (uint32_t)(ks > 0);
                        mma_tf32_cg2(tmem,        ad + ks * 2, b0d + ks * 2, e);
                        mma_tf32_cg2(tmem + 256u, ad + ks * 2, b1d + ks * 2, e);
                    }
                    TCGEN05_COMMIT_MC_CG2(sb + DONE_OFF(s), 0x3);
                    if (++s == STAGES) { s = 0; ph ^= 1; }
                }
            }
        }
    }

    __syncthreads();
    if (wid == 8) {
        asm volatile("tcgen05.dealloc.cta_group::2.sync.aligned.b32 %0, %1;"
                     :: "r"(tmem), "r"((uint32_t)TMEM_COLS));
    }
    CLUSTER_SYNC();

#else
    // ======================= mma.sync tf32 fallback ========================
    // Two sequential 256-wide N halves of the 512-wide tile.
    const float* gA0 = x + (size_t)m0 * K;

    const int wm = (wid & 1) * 64;
    const int wn = (wid >> 1) * 64;
    const int g  = lid >> 2;
    const int t  = lid & 3;

    for (int h = 0; h < 2; h++) {
        const float* gB0 = g_wm + (size_t)(n0 + h * 256) * K;

        float acc[4][8][4];
#pragma unroll
        for (int i = 0; i < 4; i++)
#pragma unroll
            for (int j = 0; j < 8; j++)
#pragma unroll
                for (int c = 0; c < 4; c++) acc[i][j][c] = 0.0f;

        if (tid < NLOAD) {
#pragma unroll
            for (int s = 0; s < 3; s++)
                load_stage_fb(sb, s, gA0 + s * BK, gB0 + s * BK, K, tid);
        }

        for (int k = 0; k < KCH; k++) {
            if (tid < NLOAD) {
                int pend = KCH - 1 - k; if (pend > 2) pend = 2;
                if (pend <= 0)      asm volatile("cp.async.wait_group 0;" ::: "memory");
                else if (pend == 1) asm volatile("cp.async.wait_group 1;" ::: "memory");
                else                asm volatile("cp.async.wait_group 2;" ::: "memory");
            }
            __syncthreads();

            if (tid < NLOAD && k + 3 < KCH) {
                const int c = k + 3;
                load_stage_fb(sb, (k + 3) & 3, gA0 + (size_t)c * BK,
                              gB0 + (size_t)c * BK, K, tid);
            }

            if (wid < 8) {
                const uint32_t sa = sb + SMEM_STAGE0 + (k & 3) * FB_STAGE_BYTES;
                const uint32_t sB = sa + FB_A_BYTES;
#pragma unroll
                for (int k8 = 0; k8 < 4; k8++) {
                    const int kc = k8 * 8;
                    uint32_t a[4][4];
#pragma unroll
                    for (int mt = 0; mt < 4; mt++) {
                        const int r0 = wm + mt * 16 + g;
                        const int c0 = kc + t;
                        a[mt][0] = lds_u32(sa + SWZ((uint32_t)(r0 * 128 + c0 * 4)));
                        a[mt][1] = lds_u32(sa + SWZ((uint32_t)((r0 + 8) * 128 + c0 * 4)));
                        a[mt][2] = lds_u32(sa + SWZ((uint32_t)(r0 * 128 + (c0 + 4) * 4)));
                        a[mt][3] = lds_u32(sa + SWZ((uint32_t)((r0 + 8) * 128 + (c0 + 4) * 4)));
                    }
                    uint32_t b[8][2];
#pragma unroll
                    for (int nt = 0; nt < 8; nt++) {
                        const int n = wn + nt * 8 + g;
                        const int ck = kc + t;
                        b[nt][0] = lds_u32(sB + SWZ((uint32_t)(n * 128 + ck * 4)));
                        b[nt][1] = lds_u32(sB + SWZ((uint32_t)(n * 128 + (ck + 4) * 4)));
                    }
#pragma unroll
                    for (int mt = 0; mt < 4; mt++)
#pragma unroll
                        for (int nt = 0; nt < 8; nt++) {
                            asm volatile(
                                "mma.sync.aligned.m16n8k8.row.col.f32.tf32.tf32.f32 "
                                "{%0,%1,%2,%3}, {%4,%5,%6,%7}, {%8,%9}, {%0,%1,%2,%3};"
                                : "+f"(acc[mt][nt][0]), "+f"(acc[mt][nt][1]),
                                  "+f"(acc[mt][nt][2]), "+f"(acc[mt][nt][3])
                                : "r"(a[mt][0]), "r"(a[mt][1]), "r"(a[mt][2]), "r"(a[mt][3]),
                                  "r"(b[nt][0]), "r"(b[nt][1]));
                        }
                }
            }
        }
        __syncthreads();

        if (wid < 8) {
#pragma unroll
            for (int mt = 0; mt < 4; mt++) {
                const int row0 = m0 + wm + mt * 16 + g;
#pragma unroll
                for (int nt = 0; nt < 8; nt++) {
                    const int col0 = n0 + h * 256 + wn + nt * 8 + t * 2;
                    const float2 bv = *reinterpret_cast<const float2*>(bias + col0);
                    float2 v0, v1;
                    v0.x = acc[mt][nt][0] + bv.x;
                    v0.y = acc[mt][nt][1] + bv.y;
                    v1.x = acc[mt][nt][2] + bv.x;
                    v1.y = acc[mt][nt][3] + bv.y;
                    *reinterpret_cast<float2*>(out + (size_t)row0 * N + col0) = v0;
                    *reinterpret_cast<float2*>(out + (size_t)(row0 + 8) * N + col0) = v1;
                }
            }
        }
        __syncthreads();
    }
#endif
}

// ---------------------------------------------------------------------------
// launch
// ---------------------------------------------------------------------------
extern "C" void kernel_launch(void* const* d_in, const int* in_sizes, int n_in,
                              void* d_out, int out_size) {
    const float* x    = (const float*)d_in[0];
    const float* w    = (const float*)d_in[1];
    const float* bias = (const float*)d_in[2];
    const float* mask = (const float*)d_in[3];
    float* out = (float*)d_out;

    const int N = in_sizes[2];                  // 4096 (D_OUT)
    const int K = in_sizes[1] / N;              // 4096 (D_IN)
    const int M = in_sizes[0] / K;              // 8192 (B*S)

    {
        int n4 = (N * K) / 4;
        prep_w_kernel<<<(n4 + 255) / 256, 256>>>((const float4*)w,
                                                 (const float4*)mask, n4);
    }

    cudaFuncSetAttribute(masked_gemm_kernel,
                         cudaFuncAttributeMaxDynamicSharedMemorySize, SMEM_TOTAL);
    dim3 grid(2, N / 512, M / 256);   // (2, 8, 32) = 512 CTAs, 256 cg2 pairs
    masked_gemm_kernel<<<grid, THREADS, SMEM_TOTAL>>>(x, bias, out, M, N, K);
}

// round 6
// speedup vs baseline: 1.2765x; 1.0020x over previous
#include <cuda_runtime.h>
#include <cuda.h>
#include <dlfcn.h>
#include <cstdint>
#include <cstddef>

// ============================================================================
// MaskedLinear: y = x @ (W*mask)^T + b ; M=8192, K=4096, N=4096 fp32.
//
// prep_w: g_wm = cvt.rna.tf32(W*mask)
// gemm  : PERSISTENT cg2 tcgen05 kind::tf32 SS GEMM, pair tile 256(M)x512(N),
//         BK=32, 4-stage ring fed by TMA (cp.async.bulk.tensor cta_group::2,
//         complete_tx -> leader full[s]).  Warp 8: TMA issue + MMA (leader) /
//         TMA issue (follower).  Warps 0-7: epilogue only.
//         148 CTAs (74 pairs) loop over 256 tiles (3-4 each).
// Fallback (non-103a PTX pass; never selected on GB300): mma.sync tf32.
// ============================================================================

#define SWZ(o) ((o) ^ (((o) >> 3) & 0x70))

static constexpr int BK = 32;                 // floats per K-chunk (128 B)
static constexpr int THREADS = 288;           // warps 0-7 epilogue, warp 8 ctrl
static constexpr int STAGES = 4;

static constexpr int A_BYTES  = 128 * 128;    // 16 KB
static constexpr int B0_BYTES = 128 * 128;
static constexpr int B1_BYTES = 128 * 128;
static constexpr int STAGE_BYTES = A_BYTES + B0_BYTES + B1_BYTES;     // 48 KB
static constexpr int SMEM_STAGE0 = 1024;
static constexpr int SMEM_TOTAL = SMEM_STAGE0 + STAGES * STAGE_BYTES; // 197632
static constexpr int TMEM_COLS = 512;
static constexpr uint32_t STAGE_TX = (uint32_t)STAGE_BYTES * 2;       // both CTAs

// idesc kind::tf32 cg2: dfmt=F32(1)<<4, atype=TF32(2)<<7, btype=TF32(2)<<10,
// N=256 -> 32<<17, M=256 -> 16<<24.
static constexpr uint32_t IDESC =
    (1u << 4) | (2u << 7) | (2u << 10) | (32u << 17) | (16u << 24);

// SW128 K-major smem descriptor: layout=SW128(2), version=1, SBO=64, LBO=1
static constexpr uint64_t DESC_BASE =
    (2ULL << 61) | (1ULL << 46) | (64ULL << 32) | (1ULL << 16);

// mbar offsets (all 8-byte slots below SMEM_STAGE0)
#define FULL_OFF(s)  (16u + (uint32_t)(s) * 8u)    // leader, count 1 + tx
#define DONE_OFF(s)  (48u + (uint32_t)(s) * 8u)    // both CTAs, count 1
#define MMAD_OFF(p)  (88u + (uint32_t)(p) * 8u)    // both CTAs, count 1
#define EPI_OFF(p)   (104u + (uint32_t)(p) * 8u)   // leader, count 16

// --- fallback layout (base sm_103 pass only; never runs on GB300) ---
static constexpr int FB_A_BYTES = 128 * 128;
static constexpr int FB_B_BYTES = 256 * 128;
static constexpr int FB_STAGE_BYTES = FB_A_BYTES + FB_B_BYTES;   // 49152
static constexpr int NLOAD = 256;

__device__ float g_wm[4096ull * 4096ull];    // 64 MiB scratch

// ---------------------------------------------------------------------------
// portable helpers
// ---------------------------------------------------------------------------
__device__ __forceinline__ uint32_t smem_u32(const void* p) {
    uint32_t a;
    asm("{ .reg .u64 t; cvta.to.shared.u64 t, %1; cvt.u32.u64 %0, t; }"
        : "=r"(a) : "l"(p));
    return a;
}

__device__ __forceinline__ float to_tf32_rn(float x) {
    uint32_t u;
    asm("cvt.rna.tf32.f32 %0, %1;" : "=r"(u) : "f"(x));
    return __uint_as_float(u);
}

__device__ __forceinline__ void cp16(uint32_t s, const float* g) {
    asm volatile("cp.async.cg.shared.global [%0], [%1], 16;"
                 :: "r"(s), "l"(__cvta_generic_to_global((const void*)g)));
}

__device__ __forceinline__ uint32_t lds_u32(uint32_t addr) {
    uint32_t v;
    asm volatile("ld.shared.b32 %0, [%1];" : "=r"(v) : "r"(addr));
    return v;
}

#define CLUSTER_SYNC() do {                                          \
    asm volatile("barrier.cluster.arrive.aligned;" ::: "memory");    \
    asm volatile("barrier.cluster.wait.aligned;" ::: "memory");      \
} while (0)

// ---------------------------------------------------------------------------
// sm_103a-only pieces
// ---------------------------------------------------------------------------
#if defined(__CUDA_ARCH_FEAT_SM103_ALL) || defined(__CUDA_ARCH_FEAT_SM100_ALL) || !defined(__CUDA_ARCH__)

__device__ __forceinline__ uint32_t elect_one() {
    uint32_t p;
    asm volatile(
        "{\n\t.reg .pred p;\n\telect.sync _|p, 0xFFFFFFFF;\n\t"
        "selp.b32 %0, 1, 0, p;\n\t}" : "=r"(p));
    return p;
}

__device__ __forceinline__ void mma_tf32_cg2(uint32_t d_tmem, uint64_t a_desc,
                                             uint64_t b_desc, uint32_t en) {
#if defined(__CUDA_ARCH__)
    asm volatile(
        "{\n\t.reg .pred p;\n\tsetp.ne.u32 p, %6, 0;\n\t"
        "tcgen05.mma.cta_group::2.kind::tf32 [%0], %1, %2, %3, "
        "{%4, %4, %4, %4, %4, %4, %4, %4}, p;\n\t}"
        :: "r"(d_tmem), "l"(a_desc), "l"(b_desc), "r"(IDESC),
           "r"(0u), "r"(0u), "r"(en)
        : "memory");
#endif
}

// 3D TMA load, cta_group::2: data -> local smem, complete_tx -> leader's mbar
__device__ __forceinline__ void tma_cg2(uint32_t dst, const void* map,
                                        int cx, int cy, uint32_t mbar) {
#if defined(__CUDA_ARCH__)
    asm volatile(
        "{\n\t.reg .b32 lb;\n\t.reg .b32 cz;\n\tmov.b32 cz, 0;\n\t"
        "and.b32 lb, %4, 0xFEFFFFFF;\n\t"
        "cp.async.bulk.tensor.3d.cta_group::2.shared::cluster.global"
        ".tile.mbarrier::complete_tx::bytes [%0], [%1, {%2, %3, cz}], [lb];\n\t}"
        :: "r"(dst), "l"(map), "r"(cx), "r"(cy), "r"(mbar)
        : "memory");
#endif
}

#define MBARRIER_INIT(addr, cnt) \
    asm volatile("mbarrier.init.shared.b64 [%0], %1;" :: "r"(addr), "r"(cnt) : "memory")

#define MBARRIER_EXPECT_TX(addr, bytes) \
    asm volatile("mbarrier.arrive.expect_tx.shared.b64 _, [%0], %1;" \
        :: "r"((uint32_t)(addr)), "r"((uint32_t)(bytes)) : "memory")

#define MBARRIER_WAIT_PARITY(addr, ph) do {                                   \
    uint32_t _m = (uint32_t)(addr); uint32_t _p = (uint32_t)(ph);             \
    uint32_t _d;                                                              \
    asm volatile("{\n\t.reg .pred p;\n\t"                                     \
        "mbarrier.try_wait.parity.acquire.cta.shared::cta.b64 p, [%1], %2;\n\t" \
        "selp.b32 %0, 1, 0, p;\n\t}" : "=r"(_d) : "r"(_m), "r"(_p) : "memory"); \
    if (!_d) {                                                                \
        asm volatile("{\n\t.reg .pred P1;\n\t"                                \
            "WL_%=:\n\t"                                                      \
            "mbarrier.try_wait.parity.acquire.cta.shared::cta.b64 P1, [%0], %1, 0x989680;\n\t" \
            "@P1 bra.uni WD_%=;\n\t"                                          \
            "bra.uni WL_%=;\n\t"                                              \
            "WD_%=:\n\t}" :: "r"(_m), "r"(_p) : "memory");                    \
    }                                                                         \
} while (0)

#define MBARRIER_ARRIVE_LOCAL(addr)                                           \
    asm volatile("mbarrier.arrive.shared.b64 _, [%0];"                        \
        :: "r"((uint32_t)(addr)) : "memory")

#define MBARRIER_ARRIVE_RANK0(addr)                                           \
    asm volatile("{\n\t.reg .b32 r;\n\t"                                      \
        "mapa.shared::cluster.u32 r, %0, 0;\n\t"                              \
        "mbarrier.arrive.shared::cluster.b64 _, [r];\n\t}"                    \
        :: "r"((uint32_t)(addr)) : "memory")

#define TCGEN05_COMMIT_MC_CG2(addr, mask)                                     \
    asm volatile("tcgen05.commit.cta_group::2.mbarrier::arrive::one.shared::cluster.multicast::cluster.b64 [%0], %1;" \
        :: "r"((uint32_t)(addr)), "h"((uint16_t)(mask)) : "memory")

#define LDTM_X32(r, addr)                                                     \
    asm volatile("tcgen05.ld.sync.aligned.32x32b.x32.b32 "                    \
        "{%0, %1, %2, %3, %4, %5, %6, %7, "                                   \
        " %8, %9, %10, %11, %12, %13, %14, %15, "                             \
        " %16, %17, %18, %19, %20, %21, %22, %23, "                           \
        " %24, %25, %26, %27, %28, %29, %30, %31}, [%32];"                    \
        : "=r"((r)[0]),  "=r"((r)[1]),  "=r"((r)[2]),  "=r"((r)[3]),          \
          "=r"((r)[4]),  "=r"((r)[5]),  "=r"((r)[6]),  "=r"((r)[7]),          \
          "=r"((r)[8]),  "=r"((r)[9]),  "=r"((r)[10]), "=r"((r)[11]),         \
          "=r"((r)[12]), "=r"((r)[13]), "=r"((r)[14]), "=r"((r)[15]),         \
          "=r"((r)[16]), "=r"((r)[17]), "=r"((r)[18]), "=r"((r)[19]),         \
          "=r"((r)[20]), "=r"((r)[21]), "=r"((r)[22]), "=r"((r)[23]),         \
          "=r"((r)[24]), "=r"((r)[25]), "=r"((r)[26]), "=r"((r)[27]),         \
          "=r"((r)[28]), "=r"((r)[29]), "=r"((r)[30]), "=r"((r)[31])          \
        : "r"(addr))

#endif // sm_103a-only pieces

// ---------------------------------------------------------------------------
// prep kernel
// ---------------------------------------------------------------------------
__global__ void prep_w_kernel(const float4* __restrict__ w,
                              const float4* __restrict__ m, int n4) {
    int i = blockIdx.x * blockDim.x + threadIdx.x;
    if (i >= n4) return;
    float4 a = w[i], b = m[i], r;
    r.x = to_tf32_rn(a.x * b.x);
    r.y = to_tf32_rn(a.y * b.y);
    r.z = to_tf32_rn(a.z * b.z);
    r.w = to_tf32_rn(a.w * b.w);
    reinterpret_cast<float4*>(g_wm)[i] = r;
}

// ---------------------------------------------------------------------------
// fallback stage load (base pass only)
// ---------------------------------------------------------------------------
__device__ __forceinline__ void load_stage_fb(uint32_t sb, int buf,
                                              const float* gA, const float* gB,
                                              int K, int ltid) {
    const uint32_t sa  = sb + SMEM_STAGE0 + buf * FB_STAGE_BYTES;
    const uint32_t sbm = sa + FB_A_BYTES;
#pragma unroll
    for (int i = 0; i < 4; i++) {
        int u = ltid + i * NLOAD;
        int row = u >> 3, seg = u & 7;
        uint32_t off = (uint32_t)(row * 128 + seg * 16);
        cp16(sa + SWZ(off), gA + (size_t)row * K + seg * 4);
    }
#pragma unroll
    for (int i = 0; i < 8; i++) {
        int u = ltid + i * NLOAD;
        int row = u >> 3, seg = u & 7;
        uint32_t off = (uint32_t)(row * 128 + seg * 16);
        cp16(sbm + SWZ(off), gB + (size_t)row * K + seg * 4);
    }
    asm volatile("cp.async.commit_group;" ::: "memory");
}

// ---------------------------------------------------------------------------
// main GEMM kernel — persistent, TMA-fed cg2
// ---------------------------------------------------------------------------
__global__ void __launch_bounds__(THREADS, 1) __cluster_dims__(2, 1, 1)
masked_gemm_kernel(const float* __restrict__ x, const float* __restrict__ bias,
                   float* __restrict__ out, int M, int N, int K,
                   const __grid_constant__ CUtensorMap tmx,
                   const __grid_constant__ CUtensorMap tmw) {
    extern __shared__ char smem[];
    const uint32_t sb = smem_u32(smem);
    const int tid = threadIdx.x;
    const int wid = tid >> 5;
    const int lid = tid & 31;
    const int rank = blockIdx.x & 1;
    const int pair = blockIdx.x >> 1;
    const int NPAIRS = (int)(gridDim.x >> 1);          // 74
    const int NT_M = M / 256;                          // 32
    const int TILES = NT_M * (N / 512);                // 256
    const int my_nt = TILES / NPAIRS + (pair < TILES % NPAIRS ? 1 : 0);

#if defined(__CUDA_ARCH_FEAT_SM103_ALL) || defined(__CUDA_ARCH_FEAT_SM100_ALL)
    // ======================== persistent TMA+cg2 path ======================
    const int tot = my_nt * 128;                       // total K-chunks

    if (wid == 8) {
        asm volatile("tcgen05.alloc.cta_group::2.sync.aligned.shared::cta.b32 [%0], %1;"
                     :: "r"(sb), "r"((uint32_t)TMEM_COLS) : "memory");
        asm volatile("tcgen05.relinquish_alloc_permit.cta_group::2.sync.aligned;");
    }
    if (tid == 0) {
#pragma unroll
        for (int s = 0; s < STAGES; s++) {
            MBARRIER_INIT(sb + FULL_OFF(s), 1);
            MBARRIER_INIT(sb + DONE_OFF(s), 1);
        }
        MBARRIER_INIT(sb + MMAD_OFF(0), 1);
        MBARRIER_INIT(sb + MMAD_OFF(1), 1);
        MBARRIER_INIT(sb + EPI_OFF(0), 16);
        MBARRIER_INIT(sb + EPI_OFF(1), 16);
    }
    __syncthreads();
    uint32_t tmem;
    asm volatile("ld.shared.b32 %0, [%1];" : "=r"(tmem) : "r"(sb));
    CLUSTER_SYNC();

    if (wid == 8) {
        const uint32_t one = elect_one();
        if (one) {
            // --- TMA issue helper state (both ranks) ---
            // chunk c -> tile t = pair + (c>>7)*NPAIRS; k = c&127
            // A coord y = (t%NT_M)*256 + rank*128 ; B0 y = (t/NT_M)*512 + rank*128
            if (rank == 0) {
                // leader: full/MMA loop with integrated TMA issue (lookahead 3)
                // prologue: chunks 0..2
                for (int c = 0; c < 3 && c < tot; c++) {
                    const int t = pair + (c >> 7) * NPAIRS;
                    const int k = c & 127;
                    const int mi = t % NT_M, ni = t / NT_M;
                    const uint32_t sa = sb + SMEM_STAGE0 + (c & 3) * STAGE_BYTES;
                    MBARRIER_EXPECT_TX(sb + FULL_OFF(c & 3), STAGE_TX);
                    tma_cg2(sa,            &tmx, k * 32, mi * 256 + rank * 128, sb + FULL_OFF(c & 3));
                    tma_cg2(sa + A_BYTES,  &tmw, k * 32, ni * 512 + rank * 128, sb + FULL_OFF(c & 3));
                    tma_cg2(sa + A_BYTES + B0_BYTES, &tmw, k * 32,
                            ni * 512 + 256 + rank * 128, sb + FULL_OFF(c & 3));
                }
                for (int c = 0; c < tot; c++) {
                    const int s = c & 3;
                    const int k = c & 127;
                    MBARRIER_WAIT_PARITY(sb + FULL_OFF(s), (c >> 2) & 1);
                    if (k == 0 && c >= 128) {
                        // previous tile's epilogue must have drained TMEM
                        const int pt = (c >> 7) - 1;
                        MBARRIER_WAIT_PARITY(sb + EPI_OFF(pt & 1), (pt >> 1) & 1);
                    }
                    const uint32_t sa = sb + SMEM_STAGE0 + s * STAGE_BYTES;
                    const uint64_t ad  = DESC_BASE | ((sa >> 4) & 0x3FFF);
                    const uint64_t b0d = DESC_BASE | (((sa + A_BYTES) >> 4) & 0x3FFF);
                    const uint64_t b1d = DESC_BASE | (((sa + A_BYTES + B0_BYTES) >> 4) & 0x3FFF);
#pragma unroll
                    for (int ks = 0; ks < 4; ks++) {
                        uint32_t e = (uint32_t)(k > 0 || ks > 0);
                        mma_tf32_cg2(tmem,        ad + ks * 2, b0d + ks * 2, e);
                        mma_tf32_cg2(tmem + 256u, ad + ks * 2, b1d + ks * 2, e);
                    }
                    TCGEN05_COMMIT_MC_CG2(sb + DONE_OFF(s), 0x3);
                    if (k == 127) {
                        const int tt = c >> 7;
                        TCGEN05_COMMIT_MC_CG2(sb + MMAD_OFF(tt & 1), 0x3);
                    }
                    if (c >= 1) {
                        MBARRIER_WAIT_PARITY(sb + DONE_OFF((c - 1) & 3),
                                             ((c - 1) >> 2) & 1);
                    }
                    const int cn = c + 3;
                    if (cn < tot) {
                        const int t = pair + (cn >> 7) * NPAIRS;
                        const int kk = cn & 127;
                        const int mi = t % NT_M, ni = t / NT_M;
                        const uint32_t sn = sb + SMEM_STAGE0 + (cn & 3) * STAGE_BYTES;
                        MBARRIER_EXPECT_TX(sb + FULL_OFF(cn & 3), STAGE_TX);
                        tma_cg2(sn,           &tmx, kk * 32, mi * 256 + rank * 128, sb + FULL_OFF(cn & 3));
                        tma_cg2(sn + A_BYTES, &tmw, kk * 32, ni * 512 + rank * 128, sb + FULL_OFF(cn & 3));
                        tma_cg2(sn + A_BYTES + B0_BYTES, &tmw, kk * 32,
                                ni * 512 + 256 + rank * 128, sb + FULL_OFF(cn & 3));
                    }
                }
            } else {
                // follower: pure TMA issue, gated on local done ring
                for (int c = 0; c < tot; c++) {
                    if (c >= STAGES) {
                        MBARRIER_WAIT_PARITY(sb + DONE_OFF((c - 4) & 3),
                                             ((c - 4) >> 2) & 1);
                    }
                    const int t = pair + (c >> 7) * NPAIRS;
                    const int k = c & 127;
                    const int mi = t % NT_M, ni = t / NT_M;
                    const uint32_t sa = sb + SMEM_STAGE0 + (c & 3) * STAGE_BYTES;
                    tma_cg2(sa,           &tmx, k * 32, mi * 256 + rank * 128, sb + FULL_OFF(c & 3));
                    tma_cg2(sa + A_BYTES, &tmw, k * 32, ni * 512 + rank * 128, sb + FULL_OFF(c & 3));
                    tma_cg2(sa + A_BYTES + B0_BYTES, &tmw, k * 32,
                            ni * 512 + 256 + rank * 128, sb + FULL_OFF(c & 3));
                }
            }
        }
    } else {
        // ------------------------- epilogue warps --------------------------
        const int sub = wid & 3;
        const int half = wid >> 2;
        for (int ti = 0; ti < my_nt; ti++) {
            MBARRIER_WAIT_PARITY(sb + MMAD_OFF(ti & 1), (ti >> 1) & 1);
            asm volatile("tcgen05.fence::after_thread_sync;" ::: "memory");
            const int t = pair + ti * NPAIRS;
            const int mi = t % NT_M, ni = t / NT_M;
            const int m = mi * 256 + rank * 128 + sub * 32 + lid;
            const int n0 = ni * 512;
#pragma unroll
            for (int cc = 0; cc < 256; cc += 32) {
                const int col = half * 256 + cc;
                uint32_t r[32];
                LDTM_X32(r, tmem + (uint32_t)col);
                asm volatile("tcgen05.wait::ld.sync.aligned;" ::: "memory");
                const float4* bp = reinterpret_cast<const float4*>(bias + n0 + col);
                float4* op = reinterpret_cast<float4*>(out + (size_t)m * N + n0 + col);
#pragma unroll
                for (int j = 0; j < 8; j++) {
                    float4 bv = bp[j];
                    float4 v;
                    v.x = __uint_as_float(r[4 * j + 0]) + bv.x;
                    v.y = __uint_as_float(r[4 * j + 1]) + bv.y;
                    v.z = __uint_as_float(r[4 * j + 2]) + bv.z;
                    v.w = __uint_as_float(r[4 * j + 3]) + bv.w;
                    op[j] = v;
                }
            }
            asm volatile("tcgen05.fence::before_thread_sync;" ::: "memory");
            if (elect_one()) {
                if (rank == 0) MBARRIER_ARRIVE_LOCAL(sb + EPI_OFF(ti & 1));
                else           MBARRIER_ARRIVE_RANK0(sb + EPI_OFF(ti & 1));
            }
        }
    }

    __syncthreads();
    CLUSTER_SYNC();
    if (wid == 8) {
        asm volatile("tcgen05.dealloc.cta_group::2.sync.aligned.b32 %0, %1;"
                     :: "r"(tmem), "r"((uint32_t)TMEM_COLS));
    }
    CLUSTER_SYNC();

#else
    // ======================= mma.sync tf32 fallback ========================
    const int wm = (wid & 1) * 64;
    const int wn = ((wid >> 1) & 3) * 64;
    const int g  = lid >> 2;
    const int t4 = lid & 3;
    const int KCH = K / BK;

    for (int ti = 0; ti < my_nt; ti++) {
        const int t = pair + ti * NPAIRS;
        const int mi = t % NT_M, ni = t / NT_M;
        const int m0 = mi * 256 + rank * 128;
        const int n0b = ni * 512;
        const float* gA0 = x + (size_t)m0 * K;

        for (int h = 0; h < 2; h++) {
            const float* gB0 = g_wm + (size_t)(n0b + h * 256) * K;

            float acc[4][8][4];
#pragma unroll
            for (int i = 0; i < 4; i++)
#pragma unroll
                for (int j = 0; j < 8; j++)
#pragma unroll
                    for (int c = 0; c < 4; c++) acc[i][j][c] = 0.0f;

            if (tid < NLOAD) {
#pragma unroll
                for (int s = 0; s < 3; s++)
                    load_stage_fb(sb, s, gA0 + s * BK, gB0 + s * BK, K, tid);
            }

            for (int k = 0; k < KCH; k++) {
                if (tid < NLOAD) {
                    int pend = KCH - 1 - k; if (pend > 2) pend = 2;
                    if (pend <= 0)      asm volatile("cp.async.wait_group 0;" ::: "memory");
                    else if (pend == 1) asm volatile("cp.async.wait_group 1;" ::: "memory");
                    else                asm volatile("cp.async.wait_group 2;" ::: "memory");
                }
                __syncthreads();

                if (tid < NLOAD && k + 3 < KCH) {
                    const int c = k + 3;
                    load_stage_fb(sb, (k + 3) & 3, gA0 + (size_t)c * BK,
                                  gB0 + (size_t)c * BK, K, tid);
                }

                if (wid < 8) {
                    const uint32_t sa = sb + SMEM_STAGE0 + (k & 3) * FB_STAGE_BYTES;
                    const uint32_t sB = sa + FB_A_BYTES;
#pragma unroll
                    for (int k8 = 0; k8 < 4; k8++) {
                        const int kc = k8 * 8;
                        uint32_t a[4][4];
#pragma unroll
                        for (int mt = 0; mt < 4; mt++) {
                            const int r0 = wm + mt * 16 + g;
                            const int c0 = kc + t4;
                            a[mt][0] = lds_u32(sa + SWZ((uint32_t)(r0 * 128 + c0 * 4)));
                            a[mt][1] = lds_u32(sa + SWZ((uint32_t)((r0 + 8) * 128 + c0 * 4)));
                            a[mt][2] = lds_u32(sa + SWZ((uint32_t)(r0 * 128 + (c0 + 4) * 4)));
                            a[mt][3] = lds_u32(sa + SWZ((uint32_t)((r0 + 8) * 128 + (c0 + 4) * 4)));
                        }
                        uint32_t b[8][2];
#pragma unroll
                        for (int nt = 0; nt < 8; nt++) {
                            const int n = wn + nt * 8 + g;
                            const int ck = kc + t4;
                            b[nt][0] = lds_u32(sB + SWZ((uint32_t)(n * 128 + ck * 4)));
                            b[nt][1] = lds_u32(sB + SWZ((uint32_t)(n * 128 + (ck + 4) * 4)));
                        }
#pragma unroll
                        for (int mt = 0; mt < 4; mt++)
#pragma unroll
                            for (int nt = 0; nt < 8; nt++) {
                                asm volatile(
                                    "mma.sync.aligned.m16n8k8.row.col.f32.tf32.tf32.f32 "
                                    "{%0,%1,%2,%3}, {%4,%5,%6,%7}, {%8,%9}, {%0,%1,%2,%3};"
                                    : "+f"(acc[mt][nt][0]), "+f"(acc[mt][nt][1]),
                                      "+f"(acc[mt][nt][2]), "+f"(acc[mt][nt][3])
                                    : "r"(a[mt][0]), "r"(a[mt][1]), "r"(a[mt][2]), "r"(a[mt][3]),
                                      "r"(b[nt][0]), "r"(b[nt][1]));
                            }
                    }
                }
            }
            __syncthreads();

            if (wid < 8) {
#pragma unroll
                for (int mt = 0; mt < 4; mt++) {
                    const int row0 = m0 + wm + mt * 16 + g;
#pragma unroll
                    for (int nt = 0; nt < 8; nt++) {
                        const int col0 = n0b + h * 256 + wn + nt * 8 + t4 * 2;
                        const float2 bv = *reinterpret_cast<const float2*>(bias + col0);
                        float2 v0, v1;
                        v0.x = acc[mt][nt][0] + bv.x;
                        v0.y = acc[mt][nt][1] + bv.y;
                        v1.x = acc[mt][nt][2] + bv.x;
                        v1.y = acc[mt][nt][3] + bv.y;
                        *reinterpret_cast<float2*>(out + (size_t)row0 * N + col0) = v0;
                        *reinterpret_cast<float2*>(out + (size_t)(row0 + 8) * N + col0) = v1;
                    }
                }
            }
            __syncthreads();
        }
    }
#endif
}

// ---------------------------------------------------------------------------
// host: tensor map encode (dlopen'd driver API) + launch
// ---------------------------------------------------------------------------
typedef CUresult (*PFN_tmEncode)(
    CUtensorMap*, CUtensorMapDataType, cuuint32_t, void*,
    const cuuint64_t*, const cuuint64_t*, const cuuint32_t*, const cuuint32_t*,
    CUtensorMapInterleave, CUtensorMapSwizzle, CUtensorMapL2promotion,
    CUtensorMapFloatOOBfill);

static PFN_tmEncode get_encoder() {
    static PFN_tmEncode fn = nullptr;
    if (!fn) {
        void* h = dlopen("libcuda.so.1", RTLD_NOW | RTLD_GLOBAL);
        if (!h) h = dlopen("libcuda.so", RTLD_NOW | RTLD_GLOBAL);
        if (h) fn = (PFN_tmEncode)dlsym(h, "cuTensorMapEncodeTiled");
    }
    return fn;
}

static void encode_map(PFN_tmEncode enc, CUtensorMap* tm, void* base,
                       uint64_t rows, uint64_t cols_elems) {
    cuuint64_t dims[3]    = {cols_elems, rows, 1};
    cuuint64_t strides[2] = {cols_elems * 4, rows * cols_elems * 4};
    cuuint32_t box[3]     = {32, 128, 1};     // 32 f32 = 128 B (SW128 limit)
    cuuint32_t estr[3]    = {1, 1, 1};
    enc(tm, CU_TENSOR_MAP_DATA_TYPE_FLOAT32, 3, base, dims, strides, box, estr,
        CU_TENSOR_MAP_INTERLEAVE_NONE, CU_TENSOR_MAP_SWIZZLE_128B,
        CU_TENSOR_MAP_L2_PROMOTION_L2_128B, CU_TENSOR_MAP_FLOAT_OOB_FILL_NONE);
}

extern "C" void kernel_launch(void* const* d_in, const int* in_sizes, int n_in,
                              void* d_out, int out_size) {
    const float* x    = (const float*)d_in[0];
    const float* w    = (const float*)d_in[1];
    const float* bias = (const float*)d_in[2];
    const float* mask = (const float*)d_in[3];
    float* out = (float*)d_out;

    const int N = in_sizes[2];                  // 4096
    const int K = in_sizes[1] / N;              // 4096
    const int M = in_sizes[0] / K;              // 8192

    {
        int n4 = (N * K) / 4;
        prep_w_kernel<<<(n4 + 255) / 256, 256>>>((const float4*)w,
                                                 (const float4*)mask, n4);
    }

    static CUtensorMap tmx, tmw;
    PFN_tmEncode enc = get_encoder();
    void* wm_ptr = nullptr;
    cudaGetSymbolAddress(&wm_ptr, g_wm);
    if (enc) {
        encode_map(enc, &tmx, (void*)x, (uint64_t)M, (uint64_t)K);
        encode_map(enc, &tmw, wm_ptr,   (uint64_t)N, (uint64_t)K);
    }

    cudaFuncSetAttribute(masked_gemm_kernel,
                         cudaFuncAttributeMaxDynamicSharedMemorySize, SMEM_TOTAL);
    masked_gemm_kernel<<<148, THREADS, SMEM_TOTAL>>>(x, bias, out, M, N, K,
                                                     tmx, tmw);
}